// round 1
// baseline (speedup 1.0000x reference)
#include <cuda_runtime.h>
#include <math.h>
#include <stdint.h>

// ============================================================================
// Sinkhorn divergence, N=M=8192, D=64.
// Strategy: precompute the 4 cost matrices once into __device__ scratch
// (they are constant across all Sinkhorn iterations), then every softmin is a
// pure streaming row-wise online-logsumexp over a 256MB fp32 matrix.
// ============================================================================

#define NMAX 8192
#define DDIM 64

static __device__ float d_Cxy[(size_t)NMAX * NMAX];  // cost(x_i, y_j), rows=x
static __device__ float d_Cyx[(size_t)NMAX * NMAX];  // transpose, rows=y
static __device__ float d_Cxx[(size_t)NMAX * NMAX];
static __device__ float d_Cyy[(size_t)NMAX * NMAX];
static __device__ float d_sq[2][NMAX];               // |x|^2, |y|^2
// potentials / temporaries:
// 0 f_aa, 1 g_bb, 2 g_ab, 3 f_ba, 4 ft, 5 gt, 6 ftaa, 7 gtbb,
// 8 f_ba_f, 9 g_ab_f, 10 f_aa_f, 11 g_bb_f
static __device__ float d_vec[12][NMAX];

// ---------------------------------------------------------------------------
// squared norms: one warp per row of 64 floats
// ---------------------------------------------------------------------------
__global__ void sqnorm_kernel(const float* __restrict__ X, float* __restrict__ out,
                              int n, int d) {
    int row = blockIdx.x * (blockDim.x >> 5) + (threadIdx.x >> 5);
    int lane = threadIdx.x & 31;
    if (row >= n) return;
    float s = 0.f;
    for (int c = lane; c < d; c += 32) {
        float v = X[(size_t)row * d + c];
        s += v * v;
    }
#pragma unroll
    for (int o = 16; o; o >>= 1) s += __shfl_xor_sync(0xFFFFFFFFu, s, o);
    if (lane == 0) out[row] = s;
}

// ---------------------------------------------------------------------------
// cost GEMM: C1[i][j] = max(0.5*sqa[i] + 0.5*sqb[j] - A_i.B_j, 0)
// Also writes the transpose into C2 (C2 may equal C1 for symmetric case,
// in which case only blocks with bi <= bj run and the lower triangle is
// filled via the transposed write).
// 128x128 tile, 256 threads, 8x8 per thread, BK=32.
// ---------------------------------------------------------------------------
#define BM 128
#define BN 128
#define BKC 32

__global__ __launch_bounds__(256) void cost_gemm_kernel(
    const float* __restrict__ A, const float* __restrict__ B,
    const float* __restrict__ sqa, const float* __restrict__ sqb,
    float* __restrict__ C1, float* __restrict__ C2,
    int nA, int nB, int d, int sym)
{
    int bj = blockIdx.x, bi = blockIdx.y;
    if (sym && bi > bj) return;

    __shared__ float As[BKC][BM + 4];   // +4 keeps rows 16B-aligned (132 floats)
    __shared__ float Bs[BKC][BN + 4];

    int tid = threadIdx.x;
    int ti = tid & 15, tj = tid >> 4;
    int i0 = ti * 8, j0 = tj * 8;

    const float* Ab = A + (size_t)bi * BM * d;
    const float* Bb = B + (size_t)bj * BN * d;

    float acc[8][8];
#pragma unroll
    for (int a = 0; a < 8; a++)
#pragma unroll
        for (int b = 0; b < 8; b++) acc[a][b] = 0.f;

    for (int kk = 0; kk < d; kk += BKC) {
        // load 128 rows x 32 cols of A and B (transposed into smem)
#pragma unroll
        for (int v = tid; v < 1024; v += 256) {
            int r = v >> 3, c4 = (v & 7) * 4;
            float4 a = *(const float4*)(Ab + (size_t)r * d + kk + c4);
            As[c4 + 0][r] = a.x; As[c4 + 1][r] = a.y;
            As[c4 + 2][r] = a.z; As[c4 + 3][r] = a.w;
            float4 b = *(const float4*)(Bb + (size_t)r * d + kk + c4);
            Bs[c4 + 0][r] = b.x; Bs[c4 + 1][r] = b.y;
            Bs[c4 + 2][r] = b.z; Bs[c4 + 3][r] = b.w;
        }
        __syncthreads();
#pragma unroll
        for (int k = 0; k < BKC; k++) {
            float4 a0 = *(const float4*)&As[k][i0];
            float4 a1 = *(const float4*)&As[k][i0 + 4];
            float4 b0 = *(const float4*)&Bs[k][j0];
            float4 b1 = *(const float4*)&Bs[k][j0 + 4];
            float av[8] = {a0.x, a0.y, a0.z, a0.w, a1.x, a1.y, a1.z, a1.w};
            float bv[8] = {b0.x, b0.y, b0.z, b0.w, b1.x, b1.y, b1.z, b1.w};
#pragma unroll
            for (int ii = 0; ii < 8; ii++)
#pragma unroll
                for (int jj = 0; jj < 8; jj++)
                    acc[ii][jj] += av[ii] * bv[jj];
        }
        __syncthreads();
    }

    float si[8], sj[8];
#pragma unroll
    for (int ii = 0; ii < 8; ii++) si[ii] = 0.5f * sqa[bi * BM + i0 + ii];
#pragma unroll
    for (int jj = 0; jj < 8; jj++) sj[jj] = 0.5f * sqb[bj * BN + j0 + jj];

    // C = max(0.5|a|^2 + 0.5|b|^2 - dot, 0)
#pragma unroll
    for (int ii = 0; ii < 8; ii++) {
        size_t off = (size_t)(bi * BM + i0 + ii) * nB + bj * BN + j0;
        float4 w0 = make_float4(
            fmaxf(si[ii] + sj[0] - acc[ii][0], 0.f),
            fmaxf(si[ii] + sj[1] - acc[ii][1], 0.f),
            fmaxf(si[ii] + sj[2] - acc[ii][2], 0.f),
            fmaxf(si[ii] + sj[3] - acc[ii][3], 0.f));
        float4 w1 = make_float4(
            fmaxf(si[ii] + sj[4] - acc[ii][4], 0.f),
            fmaxf(si[ii] + sj[5] - acc[ii][5], 0.f),
            fmaxf(si[ii] + sj[6] - acc[ii][6], 0.f),
            fmaxf(si[ii] + sj[7] - acc[ii][7], 0.f));
        *(float4*)(C1 + off) = w0;
        *(float4*)(C1 + off + 4) = w1;
    }
    // transposed write
#pragma unroll
    for (int jj = 0; jj < 8; jj++) {
        size_t off = (size_t)(bj * BN + j0 + jj) * nA + bi * BM + i0;
        float4 w0 = make_float4(
            fmaxf(si[0] + sj[jj] - acc[0][jj], 0.f),
            fmaxf(si[1] + sj[jj] - acc[1][jj], 0.f),
            fmaxf(si[2] + sj[jj] - acc[2][jj], 0.f),
            fmaxf(si[3] + sj[jj] - acc[3][jj], 0.f));
        float4 w1 = make_float4(
            fmaxf(si[4] + sj[jj] - acc[4][jj], 0.f),
            fmaxf(si[5] + sj[jj] - acc[5][jj], 0.f),
            fmaxf(si[6] + sj[jj] - acc[6][jj], 0.f),
            fmaxf(si[7] + sj[jj] - acc[7][jj], 0.f));
        *(float4*)(C2 + off) = w0;
        *(float4*)(C2 + off + 4) = w1;
    }
}

// ---------------------------------------------------------------------------
// softmin: out[i] = -eps * logsumexp_j( h_j - C[i][j]/eps ),
//          h_j = logw (+ pot[j]/eps if pot != null)
// One warp per row, 8 rows per 256-thread block; h staged in smem.
// ---------------------------------------------------------------------------
__global__ __launch_bounds__(256) void softmin_kernel(
    const float* __restrict__ C, const float* __restrict__ pot,
    const float* __restrict__ eps_list, int eps_idx, float logw,
    float* __restrict__ out, int n, int m)
{
    __shared__ float sh[NMAX];
    float eps = eps_list[eps_idx];
    float inv_eps = 1.0f / eps;

    for (int j = threadIdx.x * 4; j < m; j += 1024) {
        float4 h;
        if (pot) {
            float4 p = *(const float4*)(pot + j);
            h = make_float4(logw + p.x * inv_eps, logw + p.y * inv_eps,
                            logw + p.z * inv_eps, logw + p.w * inv_eps);
        } else {
            h = make_float4(logw, logw, logw, logw);
        }
        *(float4*)(sh + j) = h;
    }
    __syncthreads();

    int row = blockIdx.x * 8 + (threadIdx.x >> 5);
    if (row >= n) return;
    int lane = threadIdx.x & 31;
    const float* Crow = C + (size_t)row * m;

    float mx = -3.4e38f, s = 0.f;
#define ONL(v) do { float _v = (v);                                      \
        if (_v > mx) { s = s * __expf(mx - _v) + 1.0f; mx = _v; }        \
        else { s += __expf(_v - mx); } } while (0)

    for (int j = lane * 4; j < m; j += 128) {
        float4 c4 = *(const float4*)(Crow + j);
        float4 h4 = *(const float4*)(sh + j);
        ONL(h4.x - c4.x * inv_eps);
        ONL(h4.y - c4.y * inv_eps);
        ONL(h4.z - c4.z * inv_eps);
        ONL(h4.w - c4.w * inv_eps);
    }
#undef ONL

    // warp-level combine of (mx, s) pairs
#pragma unroll
    for (int o = 16; o; o >>= 1) {
        float m2 = __shfl_xor_sync(0xFFFFFFFFu, mx, o);
        float s2 = __shfl_xor_sync(0xFFFFFFFFu, s, o);
        float mn = fmaxf(mx, m2);
        s = s * __expf(mx - mn) + s2 * __expf(m2 - mn);
        mx = mn;
    }
    if (lane == 0) out[row] = -eps * (mx + __logf(s));
}

// ---------------------------------------------------------------------------
// symmetrized dual update (geomloss averaging)
// ---------------------------------------------------------------------------
__global__ void combine_kernel(int n) {
    int i = blockIdx.x * blockDim.x + threadIdx.x;
    if (i >= n) return;
    d_vec[0][i] = 0.5f * (d_vec[0][i] + d_vec[6][i]);  // f_aa <- avg(f_aa, ftaa)
    d_vec[1][i] = 0.5f * (d_vec[1][i] + d_vec[7][i]);  // g_bb <- avg(g_bb, gtbb)
    d_vec[2][i] = 0.5f * (d_vec[2][i] + d_vec[5][i]);  // g_ab <- avg(g_ab, gt)
    d_vec[3][i] = 0.5f * (d_vec[3][i] + d_vec[4][i]);  // f_ba <- avg(f_ba, ft)
}

// ---------------------------------------------------------------------------
// result = mean(f_ba_f - f_aa_f) + mean(g_ab_f - g_bb_f)
// ---------------------------------------------------------------------------
__global__ void final_reduce_kernel(float* __restrict__ out, int n) {
    __shared__ float red[256];
    float s = 0.f;
    for (int i = threadIdx.x; i < n; i += 256)
        s += (d_vec[8][i] - d_vec[10][i]) + (d_vec[9][i] - d_vec[11][i]);
    red[threadIdx.x] = s;
    __syncthreads();
    for (int o = 128; o; o >>= 1) {
        if (threadIdx.x < o) red[threadIdx.x] += red[threadIdx.x + o];
        __syncthreads();
    }
    if (threadIdx.x == 0) out[0] = red[0] / (float)n;
}

// ---------------------------------------------------------------------------
// host driver (graph-capturable: kernel launches only)
// ---------------------------------------------------------------------------
extern "C" void kernel_launch(void* const* d_in, const int* in_sizes, int n_in,
                              void* d_out, int out_size) {
    const float* gx = (const float*)d_in[0];
    const float* gy = (const float*)d_in[1];
    const float* eps = (const float*)d_in[2];
    int N = in_sizes[0] / DDIM;
    int M = in_sizes[1] / DDIM;
    int L = in_sizes[2];
    if (N > NMAX || M > NMAX) return;

    float *Cxy, *Cyx, *Cxx, *Cyy, *sq, *vec;
    cudaGetSymbolAddress((void**)&Cxy, d_Cxy);
    cudaGetSymbolAddress((void**)&Cyx, d_Cyx);
    cudaGetSymbolAddress((void**)&Cxx, d_Cxx);
    cudaGetSymbolAddress((void**)&Cyy, d_Cyy);
    cudaGetSymbolAddress((void**)&sq, d_sq);
    cudaGetSymbolAddress((void**)&vec, d_vec);
    float* sqx = sq;
    float* sqy = sq + NMAX;
#define V(i) (vec + (size_t)(i) * NMAX)

    float alog = -logf((float)N);
    float blog = -logf((float)M);

    // --- precompute cost matrices ---
    sqnorm_kernel<<<(N + 7) / 8, 256>>>(gx, sqx, N, DDIM);
    sqnorm_kernel<<<(M + 7) / 8, 256>>>(gy, sqy, M, DDIM);

    dim3 gxy(M / BM, N / BM);
    cost_gemm_kernel<<<gxy, 256>>>(gx, gy, sqx, sqy, Cxy, Cyx, N, M, DDIM, 0);
    dim3 gxx(N / BM, N / BM);
    cost_gemm_kernel<<<gxx, 256>>>(gx, gx, sqx, sqx, Cxx, Cxx, N, N, DDIM, 1);
    dim3 gyy(M / BM, M / BM);
    cost_gemm_kernel<<<gyy, 256>>>(gy, gy, sqy, sqy, Cyy, Cyy, M, M, DDIM, 1);

    int gbN = N / 8, gbM = M / 8;

    // --- init at eps_list[0] ---
    softmin_kernel<<<gbN, 256>>>(Cxx, nullptr, eps, 0, alog, V(0), N, N); // f_aa
    softmin_kernel<<<gbM, 256>>>(Cyy, nullptr, eps, 0, blog, V(1), M, M); // g_bb
    softmin_kernel<<<gbM, 256>>>(Cyx, nullptr, eps, 0, alog, V(2), M, N); // g_ab
    softmin_kernel<<<gbN, 256>>>(Cxy, nullptr, eps, 0, blog, V(3), N, M); // f_ba

    // --- Sinkhorn scan over eps_list ---
    for (int k = 0; k < L; k++) {
        softmin_kernel<<<gbN, 256>>>(Cxy, V(2), eps, k, blog, V(4), N, M); // ft
        softmin_kernel<<<gbM, 256>>>(Cyx, V(3), eps, k, alog, V(5), M, N); // gt
        softmin_kernel<<<gbN, 256>>>(Cxx, V(0), eps, k, alog, V(6), N, N); // ftaa
        softmin_kernel<<<gbM, 256>>>(Cyy, V(1), eps, k, blog, V(7), M, M); // gtbb
        combine_kernel<<<(N + 255) / 256, 256>>>(N);
    }

    // --- final extrapolation at eps_list[L-1] ---
    softmin_kernel<<<gbN, 256>>>(Cxy, V(2), eps, L - 1, blog, V(8), N, M);  // f_ba_f
    softmin_kernel<<<gbM, 256>>>(Cyx, V(3), eps, L - 1, alog, V(9), M, N);  // g_ab_f
    softmin_kernel<<<gbN, 256>>>(Cxx, V(0), eps, L - 1, alog, V(10), N, N); // f_aa_f
    softmin_kernel<<<gbM, 256>>>(Cyy, V(1), eps, L - 1, blog, V(11), M, M); // g_bb_f

    final_reduce_kernel<<<1, 256>>>((float*)d_out, N);
#undef V
}

// round 3
// speedup vs baseline: 1.5788x; 1.5788x over previous
#include <cuda_runtime.h>
#include <math.h>
#include <stdint.h>

// ============================================================================
// Sinkhorn divergence, N=M=8192, D=64.
// Precompute the 4 cost matrices once (constant across Sinkhorn iterations),
// then every softmin is a streaming row-wise logsumexp at DRAM bandwidth.
// Round 2: branchless chunked LSE in exp2 domain + warp-uniform skip vote,
// 4 softmins fused per launch, dual-averaging folded into the epilogue.
// ============================================================================

#define NMAX 8192
#define DDIM 64
#define LOG2E 1.4426950408889634f
#define LN2   0.6931471805599453f

static __device__ float d_Cxy[(size_t)NMAX * NMAX];
static __device__ float d_Cyx[(size_t)NMAX * NMAX];
static __device__ float d_Cxx[(size_t)NMAX * NMAX];
static __device__ float d_Cyy[(size_t)NMAX * NMAX];
static __device__ float d_sq[2][NMAX];
// slots: set0 = 0..3 (f_aa,g_bb,g_ab,f_ba), set1 = 4..7 (ping-pong),
//        8..11 = final extrapolated potentials
static __device__ float d_vec[12][NMAX];

// ---------------------------------------------------------------------------
__global__ void sqnorm_kernel(const float* __restrict__ X, float* __restrict__ out,
                              int n, int d) {
    int row = blockIdx.x * (blockDim.x >> 5) + (threadIdx.x >> 5);
    int lane = threadIdx.x & 31;
    if (row >= n) return;
    float s = 0.f;
    for (int c = lane; c < d; c += 32) {
        float v = X[(size_t)row * d + c];
        s += v * v;
    }
#pragma unroll
    for (int o = 16; o; o >>= 1) s += __shfl_xor_sync(0xFFFFFFFFu, s, o);
    if (lane == 0) out[row] = s;
}

// ---------------------------------------------------------------------------
// cost GEMM: C1[i][j] = max(0.5*sqa[i] + 0.5*sqb[j] - A_i.B_j, 0), also writes
// transpose into C2 (C2==C1 + sym=1 -> only upper-triangular blocks run).
// ---------------------------------------------------------------------------
#define BM 128
#define BN 128
#define BKC 32

__global__ __launch_bounds__(256) void cost_gemm_kernel(
    const float* __restrict__ A, const float* __restrict__ B,
    const float* __restrict__ sqa, const float* __restrict__ sqb,
    float* __restrict__ C1, float* __restrict__ C2,
    int nA, int nB, int d, int sym)
{
    int bj = blockIdx.x, bi = blockIdx.y;
    if (sym && bi > bj) return;

    __shared__ float As[BKC][BM + 4];
    __shared__ float Bs[BKC][BN + 4];

    int tid = threadIdx.x;
    int ti = tid & 15, tj = tid >> 4;
    int i0 = ti * 8, j0 = tj * 8;

    const float* Ab = A + (size_t)bi * BM * d;
    const float* Bb = B + (size_t)bj * BN * d;

    float acc[8][8];
#pragma unroll
    for (int a = 0; a < 8; a++)
#pragma unroll
        for (int b = 0; b < 8; b++) acc[a][b] = 0.f;

    for (int kk = 0; kk < d; kk += BKC) {
#pragma unroll
        for (int v = tid; v < 1024; v += 256) {
            int r = v >> 3, c4 = (v & 7) * 4;
            float4 a = *(const float4*)(Ab + (size_t)r * d + kk + c4);
            As[c4 + 0][r] = a.x; As[c4 + 1][r] = a.y;
            As[c4 + 2][r] = a.z; As[c4 + 3][r] = a.w;
            float4 b = *(const float4*)(Bb + (size_t)r * d + kk + c4);
            Bs[c4 + 0][r] = b.x; Bs[c4 + 1][r] = b.y;
            Bs[c4 + 2][r] = b.z; Bs[c4 + 3][r] = b.w;
        }
        __syncthreads();
#pragma unroll
        for (int k = 0; k < BKC; k++) {
            float4 a0 = *(const float4*)&As[k][i0];
            float4 a1 = *(const float4*)&As[k][i0 + 4];
            float4 b0 = *(const float4*)&Bs[k][j0];
            float4 b1 = *(const float4*)&Bs[k][j0 + 4];
            float av[8] = {a0.x, a0.y, a0.z, a0.w, a1.x, a1.y, a1.z, a1.w};
            float bv[8] = {b0.x, b0.y, b0.z, b0.w, b1.x, b1.y, b1.z, b1.w};
#pragma unroll
            for (int ii = 0; ii < 8; ii++)
#pragma unroll
                for (int jj = 0; jj < 8; jj++)
                    acc[ii][jj] += av[ii] * bv[jj];
        }
        __syncthreads();
    }

    float si[8], sj[8];
#pragma unroll
    for (int ii = 0; ii < 8; ii++) si[ii] = 0.5f * sqa[bi * BM + i0 + ii];
#pragma unroll
    for (int jj = 0; jj < 8; jj++) sj[jj] = 0.5f * sqb[bj * BN + j0 + jj];

#pragma unroll
    for (int ii = 0; ii < 8; ii++) {
        size_t off = (size_t)(bi * BM + i0 + ii) * nB + bj * BN + j0;
        float4 w0 = make_float4(
            fmaxf(si[ii] + sj[0] - acc[ii][0], 0.f),
            fmaxf(si[ii] + sj[1] - acc[ii][1], 0.f),
            fmaxf(si[ii] + sj[2] - acc[ii][2], 0.f),
            fmaxf(si[ii] + sj[3] - acc[ii][3], 0.f));
        float4 w1 = make_float4(
            fmaxf(si[ii] + sj[4] - acc[ii][4], 0.f),
            fmaxf(si[ii] + sj[5] - acc[ii][5], 0.f),
            fmaxf(si[ii] + sj[6] - acc[ii][6], 0.f),
            fmaxf(si[ii] + sj[7] - acc[ii][7], 0.f));
        *(float4*)(C1 + off) = w0;
        *(float4*)(C1 + off + 4) = w1;
    }
#pragma unroll
    for (int jj = 0; jj < 8; jj++) {
        size_t off = (size_t)(bj * BN + j0 + jj) * nA + bi * BM + i0;
        float4 w0 = make_float4(
            fmaxf(si[0] + sj[jj] - acc[0][jj], 0.f),
            fmaxf(si[1] + sj[jj] - acc[1][jj], 0.f),
            fmaxf(si[2] + sj[jj] - acc[2][jj], 0.f),
            fmaxf(si[3] + sj[jj] - acc[3][jj], 0.f));
        float4 w1 = make_float4(
            fmaxf(si[4] + sj[jj] - acc[4][jj], 0.f),
            fmaxf(si[5] + sj[jj] - acc[5][jj], 0.f),
            fmaxf(si[6] + sj[jj] - acc[6][jj], 0.f),
            fmaxf(si[7] + sj[jj] - acc[7][jj], 0.f));
        *(float4*)(C2 + off) = w0;
        *(float4*)(C2 + off + 4) = w1;
    }
}

// ---------------------------------------------------------------------------
// quad softmin: 4 independent jobs in one launch (blockIdx.y = job).
// out[i] = -eps * log sum_j exp(h_j - C[i][j]/eps), h_j = logw (+ pot_j/eps)
// optional epilogue blend: out = 0.5 * (oldv + result)
// Branchless chunked online-LSE in exp2 domain; warp-uniform skip vote.
// ---------------------------------------------------------------------------
struct SMJobs {
    const float* C[4];
    const float* pot[4];    // may be null
    const float* oldv[4];   // may be null (no blend)
    float*       out[4];
    float        logw[4];   // natural log weights
    int          n[4];
    int          m[4];
};

__global__ __launch_bounds__(256) void softmin4_kernel(
    SMJobs jobs, const float* __restrict__ eps_list, int eps_idx)
{
    int job = blockIdx.y;
    int n = jobs.n[job], m = jobs.m[job];
    const float* __restrict__ C = jobs.C[job];
    const float* __restrict__ pot = jobs.pot[job];

    __shared__ float sh[NMAX];
    float eps = eps_list[eps_idx];
    float ie2 = LOG2E / eps;               // log2(e)/eps
    float lw2 = jobs.logw[job] * LOG2E;

    // stage h (log2 domain) into smem
    for (int j = threadIdx.x * 4; j < m; j += 1024) {
        float4 h;
        if (pot) {
            float4 p = *(const float4*)(pot + j);
            h = make_float4(fmaf(p.x, ie2, lw2), fmaf(p.y, ie2, lw2),
                            fmaf(p.z, ie2, lw2), fmaf(p.w, ie2, lw2));
        } else {
            h = make_float4(lw2, lw2, lw2, lw2);
        }
        *(float4*)(sh + j) = h;
    }
    __syncthreads();

    int row = blockIdx.x * 8 + (threadIdx.x >> 5);
    if (row >= n) return;
    int lane = threadIdx.x & 31;
    const float* __restrict__ Crow = C + (size_t)row * m;

    float mx0 = -3.4e38f, s0 = 0.f;
    float mx1 = -3.4e38f, s1 = 0.f;

#pragma unroll 4
    for (int j0 = lane * 4; j0 < m; j0 += 256) {
        // chunk A
        {
            float4 c = *(const float4*)(Crow + j0);
            float4 h = *(const float4*)(sh + j0);
            float v0 = fmaf(c.x, -ie2, h.x);
            float v1 = fmaf(c.y, -ie2, h.y);
            float v2 = fmaf(c.z, -ie2, h.z);
            float v3 = fmaf(c.w, -ie2, h.w);
            float m4 = fmaxf(fmaxf(v0, v1), fmaxf(v2, v3));
            if (__any_sync(0xFFFFFFFFu, m4 > mx0 - 20.f)) {
                float mn = fmaxf(mx0, m4);
                float p = exp2f(v0 - mn) + exp2f(v1 - mn)
                        + exp2f(v2 - mn) + exp2f(v3 - mn);
                s0 = fmaf(s0, exp2f(mx0 - mn), p);
                mx0 = mn;
            }
        }
        // chunk B (independent accumulator for ILP)
        {
            int j1 = j0 + 128;
            float4 c = *(const float4*)(Crow + j1);
            float4 h = *(const float4*)(sh + j1);
            float v0 = fmaf(c.x, -ie2, h.x);
            float v1 = fmaf(c.y, -ie2, h.y);
            float v2 = fmaf(c.z, -ie2, h.z);
            float v3 = fmaf(c.w, -ie2, h.w);
            float m4 = fmaxf(fmaxf(v0, v1), fmaxf(v2, v3));
            if (__any_sync(0xFFFFFFFFu, m4 > mx1 - 20.f)) {
                float mn = fmaxf(mx1, m4);
                float p = exp2f(v0 - mn) + exp2f(v1 - mn)
                        + exp2f(v2 - mn) + exp2f(v3 - mn);
                s1 = fmaf(s1, exp2f(mx1 - mn), p);
                mx1 = mn;
            }
        }
    }

    // merge the two accumulators
    float mx = fmaxf(mx0, mx1);
    float s = fmaf(s0, exp2f(mx0 - mx), s1 * exp2f(mx1 - mx));

    // warp reduction of (mx, s)
#pragma unroll
    for (int o = 16; o; o >>= 1) {
        float m2 = __shfl_xor_sync(0xFFFFFFFFu, mx, o);
        float s2 = __shfl_xor_sync(0xFFFFFFFFu, s, o);
        float mn = fmaxf(mx, m2);
        s = fmaf(s, exp2f(mx - mn), s2 * exp2f(m2 - mn));
        mx = mn;
    }
    if (lane == 0) {
        float res = -eps * LN2 * (mx + __log2f(s));
        const float* ov = jobs.oldv[job];
        jobs.out[job][row] = ov ? 0.5f * (ov[row] + res) : res;
    }
}

// ---------------------------------------------------------------------------
__global__ void final_reduce_kernel(float* __restrict__ out, int n) {
    __shared__ float red[256];
    float s = 0.f;
    for (int i = threadIdx.x; i < n; i += 256)
        s += (d_vec[8][i] - d_vec[10][i]) + (d_vec[9][i] - d_vec[11][i]);
    red[threadIdx.x] = s;
    __syncthreads();
    for (int o = 128; o; o >>= 1) {
        if (threadIdx.x < o) red[threadIdx.x] += red[threadIdx.x + o];
        __syncthreads();
    }
    if (threadIdx.x == 0) out[0] = red[0] / (float)n;
}

// ---------------------------------------------------------------------------
extern "C" void kernel_launch(void* const* d_in, const int* in_sizes, int n_in,
                              void* d_out, int out_size) {
    const float* gx = (const float*)d_in[0];
    const float* gy = (const float*)d_in[1];
    const float* eps = (const float*)d_in[2];
    int N = in_sizes[0] / DDIM;
    int M = in_sizes[1] / DDIM;
    int L = in_sizes[2];
    if (N > NMAX || M > NMAX) return;

    float *Cxy, *Cyx, *Cxx, *Cyy, *sq, *vec;
    cudaGetSymbolAddress((void**)&Cxy, d_Cxy);
    cudaGetSymbolAddress((void**)&Cyx, d_Cyx);
    cudaGetSymbolAddress((void**)&Cxx, d_Cxx);
    cudaGetSymbolAddress((void**)&Cyy, d_Cyy);
    cudaGetSymbolAddress((void**)&sq, d_sq);
    cudaGetSymbolAddress((void**)&vec, d_vec);
    float* sqx = sq;
    float* sqy = sq + NMAX;
#define V(i) (vec + (size_t)(i) * NMAX)

    float alog = -logf((float)N);
    float blog = -logf((float)M);

    // --- cost matrices ---
    sqnorm_kernel<<<(N + 7) / 8, 256>>>(gx, sqx, N, DDIM);
    sqnorm_kernel<<<(M + 7) / 8, 256>>>(gy, sqy, M, DDIM);

    dim3 gxy(M / BM, N / BM);
    cost_gemm_kernel<<<gxy, 256>>>(gx, gy, sqx, sqy, Cxy, Cyx, N, M, DDIM, 0);
    dim3 gxx(N / BM, N / BM);
    cost_gemm_kernel<<<gxx, 256>>>(gx, gx, sqx, sqx, Cxx, Cxx, N, N, DDIM, 1);
    dim3 gyy(M / BM, M / BM);
    cost_gemm_kernel<<<gyy, 256>>>(gy, gy, sqy, sqy, Cyy, Cyy, M, M, DDIM, 1);

    int gbN = N / 8;

    // --- init at eps_list[0] into set0: f_aa,g_bb,g_ab,f_ba = V(0..3) ---
    {
        SMJobs jb;
        jb.C[0] = Cxx; jb.pot[0] = nullptr; jb.oldv[0] = nullptr; jb.out[0] = V(0);
        jb.logw[0] = alog; jb.n[0] = N; jb.m[0] = N;
        jb.C[1] = Cyy; jb.pot[1] = nullptr; jb.oldv[1] = nullptr; jb.out[1] = V(1);
        jb.logw[1] = blog; jb.n[1] = M; jb.m[1] = M;
        jb.C[2] = Cyx; jb.pot[2] = nullptr; jb.oldv[2] = nullptr; jb.out[2] = V(2);
        jb.logw[2] = alog; jb.n[2] = M; jb.m[2] = N;
        jb.C[3] = Cxy; jb.pot[3] = nullptr; jb.oldv[3] = nullptr; jb.out[3] = V(3);
        jb.logw[3] = blog; jb.n[3] = N; jb.m[3] = M;
        softmin4_kernel<<<dim3(gbN, 4), 256>>>(jb, eps, 0);
    }

    // --- Sinkhorn iterations (ping-pong set0 <-> set1, blend in epilogue) ---
    int cur = 0;
    for (int k = 0; k < L; k++) {
        int oth = cur ^ 4;
        SMJobs jb;
        // f_aa' = 0.5*(f_aa + softmin(Cxx, a_log + f_aa/eps))
        jb.C[0] = Cxx; jb.pot[0] = V(cur + 0); jb.oldv[0] = V(cur + 0);
        jb.out[0] = V(oth + 0); jb.logw[0] = alog; jb.n[0] = N; jb.m[0] = N;
        // g_bb' = 0.5*(g_bb + softmin(Cyy, b_log + g_bb/eps))
        jb.C[1] = Cyy; jb.pot[1] = V(cur + 1); jb.oldv[1] = V(cur + 1);
        jb.out[1] = V(oth + 1); jb.logw[1] = blog; jb.n[1] = M; jb.m[1] = M;
        // g_ab' = 0.5*(g_ab + softmin(Cyx, a_log + f_ba/eps))
        jb.C[2] = Cyx; jb.pot[2] = V(cur + 3); jb.oldv[2] = V(cur + 2);
        jb.out[2] = V(oth + 2); jb.logw[2] = alog; jb.n[2] = M; jb.m[2] = N;
        // f_ba' = 0.5*(f_ba + softmin(Cxy, b_log + g_ab/eps))
        jb.C[3] = Cxy; jb.pot[3] = V(cur + 2); jb.oldv[3] = V(cur + 3);
        jb.out[3] = V(oth + 3); jb.logw[3] = blog; jb.n[3] = N; jb.m[3] = M;
        softmin4_kernel<<<dim3(gbN, 4), 256>>>(jb, eps, k);
        cur = oth;
    }

    // --- final extrapolation at eps_list[L-1] ---
    {
        SMJobs jb;
        // f_ba_f = softmin(Cxy, b_log + g_ab/eps) -> V(8)
        jb.C[0] = Cxy; jb.pot[0] = V(cur + 2); jb.oldv[0] = nullptr; jb.out[0] = V(8);
        jb.logw[0] = blog; jb.n[0] = N; jb.m[0] = M;
        // g_ab_f = softmin(Cyx, a_log + f_ba/eps) -> V(9)
        jb.C[1] = Cyx; jb.pot[1] = V(cur + 3); jb.oldv[1] = nullptr; jb.out[1] = V(9);
        jb.logw[1] = alog; jb.n[1] = M; jb.m[1] = N;
        // f_aa_f = softmin(Cxx, a_log + f_aa/eps) -> V(10)
        jb.C[2] = Cxx; jb.pot[2] = V(cur + 0); jb.oldv[2] = nullptr; jb.out[2] = V(10);
        jb.logw[2] = alog; jb.n[2] = N; jb.m[2] = N;
        // g_bb_f = softmin(Cyy, b_log + g_bb/eps) -> V(11)
        jb.C[3] = Cyy; jb.pot[3] = V(cur + 1); jb.oldv[3] = nullptr; jb.out[3] = V(11);
        jb.logw[3] = blog; jb.n[3] = M; jb.m[3] = M;
        softmin4_kernel<<<dim3(gbN, 4), 256>>>(jb, eps, L - 1);
    }

    final_reduce_kernel<<<1, 256>>>((float*)d_out, N);
#undef V
}

// round 4
// speedup vs baseline: 1.7703x; 1.1213x over previous
#include <cuda_runtime.h>
#include <math.h>
#include <stdint.h>

// ============================================================================
// Sinkhorn divergence, N=M=8192, D=64.
// Round 3: tile-based two-stage LSE.
//  - C_yx eliminated: one pass over C_xy produces row-LSE (ft) AND col-LSE (gt).
//  - C_xx / C_yy: only upper-triangular tiles stored & read (symmetry).
//  => softmin traffic per iteration: 2 matrix-reads instead of 4.
// ============================================================================

#define NMAX 8192
#define DDIM 64
#define LOG2E 1.4426950408889634f
#define LN2   0.6931471805599453f

static __device__ float d_Cxy[(size_t)NMAX * NMAX];
static __device__ float d_Cxx[(size_t)NMAX * NMAX];   // upper-tri tiles only
static __device__ float d_Cyy[(size_t)NMAX * NMAX];   // upper-tri tiles only
static __device__ float d_sq[2][NMAX];
// 0 f_aa, 1 g_bb, 2 g_ab, 3 f_ba (set0); 4..7 set1; 8..11 final potentials
static __device__ float d_vec[12][NMAX];
// partial (max, sum) buffers: [row][slot], 64 slots (tiles) per row
static __device__ float2 d_Pr[(size_t)NMAX * 64];
static __device__ float2 d_Pc[(size_t)NMAX * 64];
static __device__ float2 d_Pxx[(size_t)NMAX * 64];
static __device__ float2 d_Pyy[(size_t)NMAX * 64];

// ---------------------------------------------------------------------------
__global__ void sqnorm_kernel(const float* __restrict__ X, float* __restrict__ out,
                              int n, int d) {
    int row = blockIdx.x * (blockDim.x >> 5) + (threadIdx.x >> 5);
    int lane = threadIdx.x & 31;
    if (row >= n) return;
    float s = 0.f;
    for (int c = lane; c < d; c += 32) {
        float v = X[(size_t)row * d + c];
        s += v * v;
    }
#pragma unroll
    for (int o = 16; o; o >>= 1) s += __shfl_xor_sync(0xFFFFFFFFu, s, o);
    if (lane == 0) out[row] = s;
}

// ---------------------------------------------------------------------------
// cost GEMM: C[i][j] = max(0.5*sqa[i] + 0.5*sqb[j] - A_i.B_j, 0)
// sym=1: only tiles bi<=bj are computed/written.
// ---------------------------------------------------------------------------
#define BM 128
#define BKC 32

__global__ __launch_bounds__(256) void cost_gemm_kernel(
    const float* __restrict__ A, const float* __restrict__ B,
    const float* __restrict__ sqa, const float* __restrict__ sqb,
    float* __restrict__ C1, int nB, int d, int sym)
{
    int bj = blockIdx.x, bi = blockIdx.y;
    if (sym && bi > bj) return;

    __shared__ float As[BKC][BM + 4];
    __shared__ float Bs[BKC][BM + 4];

    int tid = threadIdx.x;
    int ti = tid & 15, tj = tid >> 4;
    int i0 = ti * 8, j0 = tj * 8;

    const float* Ab = A + (size_t)bi * BM * d;
    const float* Bb = B + (size_t)bj * BM * d;

    float acc[8][8];
#pragma unroll
    for (int a = 0; a < 8; a++)
#pragma unroll
        for (int b = 0; b < 8; b++) acc[a][b] = 0.f;

    for (int kk = 0; kk < d; kk += BKC) {
#pragma unroll
        for (int v = tid; v < 1024; v += 256) {
            int r = v >> 3, c4 = (v & 7) * 4;
            float4 a = *(const float4*)(Ab + (size_t)r * d + kk + c4);
            As[c4 + 0][r] = a.x; As[c4 + 1][r] = a.y;
            As[c4 + 2][r] = a.z; As[c4 + 3][r] = a.w;
            float4 b = *(const float4*)(Bb + (size_t)r * d + kk + c4);
            Bs[c4 + 0][r] = b.x; Bs[c4 + 1][r] = b.y;
            Bs[c4 + 2][r] = b.z; Bs[c4 + 3][r] = b.w;
        }
        __syncthreads();
#pragma unroll
        for (int k = 0; k < BKC; k++) {
            float4 a0 = *(const float4*)&As[k][i0];
            float4 a1 = *(const float4*)&As[k][i0 + 4];
            float4 b0 = *(const float4*)&Bs[k][j0];
            float4 b1 = *(const float4*)&Bs[k][j0 + 4];
            float av[8] = {a0.x, a0.y, a0.z, a0.w, a1.x, a1.y, a1.z, a1.w};
            float bv[8] = {b0.x, b0.y, b0.z, b0.w, b1.x, b1.y, b1.z, b1.w};
#pragma unroll
            for (int ii = 0; ii < 8; ii++)
#pragma unroll
                for (int jj = 0; jj < 8; jj++)
                    acc[ii][jj] += av[ii] * bv[jj];
        }
        __syncthreads();
    }

    float si[8], sj[8];
#pragma unroll
    for (int ii = 0; ii < 8; ii++) si[ii] = 0.5f * sqa[bi * BM + i0 + ii];
#pragma unroll
    for (int jj = 0; jj < 8; jj++) sj[jj] = 0.5f * sqb[bj * BM + j0 + jj];

#pragma unroll
    for (int ii = 0; ii < 8; ii++) {
        size_t off = (size_t)(bi * BM + i0 + ii) * nB + bj * BM + j0;
        float4 w0 = make_float4(
            fmaxf(si[ii] + sj[0] - acc[ii][0], 0.f),
            fmaxf(si[ii] + sj[1] - acc[ii][1], 0.f),
            fmaxf(si[ii] + sj[2] - acc[ii][2], 0.f),
            fmaxf(si[ii] + sj[3] - acc[ii][3], 0.f));
        float4 w1 = make_float4(
            fmaxf(si[ii] + sj[4] - acc[ii][4], 0.f),
            fmaxf(si[ii] + sj[5] - acc[ii][5], 0.f),
            fmaxf(si[ii] + sj[6] - acc[ii][6], 0.f),
            fmaxf(si[ii] + sj[7] - acc[ii][7], 0.f));
        *(float4*)(C1 + off) = w0;
        *(float4*)(C1 + off + 4) = w1;
    }
}

// ---------------------------------------------------------------------------
// tile LSE kernel: 128x128 tile, one global read serves row-LSE and col-LSE.
//   row-LSE of row i uses   h_j = lwc*LOG2E + potc[j]*LOG2E/eps  (cols)
//   col-LSE of col j uses   h_i = lwr*LOG2E + potr[i]*LOG2E/eps  (rows)
// Writes partials: Prow[row*64 + bj] and Pcol[col*64 + bi] as (max2, sum).
// sym=1: only bi<=bj tiles run; Pcol==Prow; diagonal tiles write rows only.
// ---------------------------------------------------------------------------
__global__ __launch_bounds__(256, 2) void tile_lse_kernel(
    const float* __restrict__ C,
    const float* __restrict__ potr, const float* __restrict__ potc,
    float lwr, float lwc,
    float2* __restrict__ Prow, float2* __restrict__ Pcol,
    const float* __restrict__ eps_list, int eps_idx, int m, int sym)
{
    int bj = blockIdx.x, bi = blockIdx.y;
    if (sym && bi > bj) return;
    int diag = (sym && bi == bj);

    float eps = eps_list[eps_idx];
    float ie2 = LOG2E / eps;
    int w = threadIdx.x >> 5, l = threadIdx.x & 31;
    int row0 = bi * 128 + w * 16;
    int col0 = bj * 128 + l * 4;

    // h over this lane's 4 columns
    float lwc2 = lwc * LOG2E;
    float hb0 = lwc2, hb1 = lwc2, hb2 = lwc2, hb3 = lwc2;
    if (potc) {
        float4 p = *(const float4*)(potc + col0);
        hb0 = fmaf(p.x, ie2, lwc2); hb1 = fmaf(p.y, ie2, lwc2);
        hb2 = fmaf(p.z, ie2, lwc2); hb3 = fmaf(p.w, ie2, lwc2);
    }
    // h over this warp's 16 rows (lane r holds row r's value, r<16)
    float lwr2 = lwr * LOG2E;
    float hav = lwr2;
    if (potr && l < 16) hav = fmaf(potr[row0 + l], ie2, lwr2);

    // load 16 rows x 4 cols into registers (single DRAM read of the tile)
    const float* base = C + (size_t)row0 * m + col0;
    float4 cd[16];
#pragma unroll
    for (int r = 0; r < 16; r++)
        cd[r] = *(const float4*)(base + (size_t)r * m);

    __shared__ float sred[8][128];
    __shared__ float cmax_s[128];

    // pass 1: row maxes (warp-reduced, kept in regs) + col maxes (cross-warp)
    float rmax[16];
    float cm0 = -3.4e38f, cm1 = -3.4e38f, cm2 = -3.4e38f, cm3 = -3.4e38f;
#pragma unroll
    for (int r = 0; r < 16; r++) {
        float u0 = cd[r].x * -ie2, u1 = cd[r].y * -ie2;
        float u2 = cd[r].z * -ie2, u3 = cd[r].w * -ie2;
        float rm = fmaxf(fmaxf(u0 + hb0, u1 + hb1), fmaxf(u2 + hb2, u3 + hb3));
#pragma unroll
        for (int o = 16; o; o >>= 1) rm = fmaxf(rm, __shfl_xor_sync(0xFFFFFFFFu, rm, o));
        rmax[r] = rm;
        float har = __shfl_sync(0xFFFFFFFFu, hav, r);
        cm0 = fmaxf(cm0, u0 + har); cm1 = fmaxf(cm1, u1 + har);
        cm2 = fmaxf(cm2, u2 + har); cm3 = fmaxf(cm3, u3 + har);
    }
    sred[w][l * 4 + 0] = cm0; sred[w][l * 4 + 1] = cm1;
    sred[w][l * 4 + 2] = cm2; sred[w][l * 4 + 3] = cm3;
    __syncthreads();
    if (threadIdx.x < 128) {
        int c = threadIdx.x;
        float mxx = sred[0][c];
#pragma unroll
        for (int ww = 1; ww < 8; ww++) mxx = fmaxf(mxx, sred[ww][c]);
        cmax_s[c] = mxx;
    }
    __syncthreads();
    float cx0 = cmax_s[l * 4 + 0], cx1 = cmax_s[l * 4 + 1];
    float cx2 = cmax_s[l * 4 + 2], cx3 = cmax_s[l * 4 + 3];

    // pass 2: exps + accumulation (data still in registers)
    float sc0 = 0.f, sc1 = 0.f, sc2 = 0.f, sc3 = 0.f;
#pragma unroll
    for (int r = 0; r < 16; r++) {
        float u0 = cd[r].x * -ie2, u1 = cd[r].y * -ie2;
        float u2 = cd[r].z * -ie2, u3 = cd[r].w * -ie2;
        float rm = rmax[r];
        float e = exp2f(u0 + hb0 - rm) + exp2f(u1 + hb1 - rm)
                + exp2f(u2 + hb2 - rm) + exp2f(u3 + hb3 - rm);
#pragma unroll
        for (int o = 16; o; o >>= 1) e += __shfl_xor_sync(0xFFFFFFFFu, e, o);
        if (l == 0) Prow[(size_t)(row0 + r) * 64 + bj] = make_float2(rm, e);
        if (!diag) {
            float har = __shfl_sync(0xFFFFFFFFu, hav, r);
            sc0 += exp2f(u0 + har - cx0); sc1 += exp2f(u1 + har - cx1);
            sc2 += exp2f(u2 + har - cx2); sc3 += exp2f(u3 + har - cx3);
        }
    }
    if (!diag) {
        __syncthreads();
        sred[w][l * 4 + 0] = sc0; sred[w][l * 4 + 1] = sc1;
        sred[w][l * 4 + 2] = sc2; sred[w][l * 4 + 3] = sc3;
        __syncthreads();
        if (threadIdx.x < 128) {
            int c = threadIdx.x;
            float s = sred[0][c] + sred[1][c] + sred[2][c] + sred[3][c]
                    + sred[4][c] + sred[5][c] + sred[6][c] + sred[7][c];
            Pcol[(size_t)(bj * 128 + c) * 64 + bi] = make_float2(cmax_s[c], s);
        }
    }
}

// ---------------------------------------------------------------------------
// stage 2: merge 64 (max,sum) partials per row -> -eps*ln2*(mx + log2 s),
// optional 0.5*(old + res) blend. grid (n/8, 4 jobs), warp per row.
// ---------------------------------------------------------------------------
struct S2Jobs {
    const float2* P[4];
    const float*  oldv[4];
    float*        out[4];
};

__global__ __launch_bounds__(256) void stage2_kernel(
    S2Jobs jb, const float* __restrict__ eps_list, int eps_idx)
{
    int job = blockIdx.y;
    float eps = eps_list[eps_idx];
    int row = blockIdx.x * 8 + (threadIdx.x >> 5);
    int l = threadIdx.x & 31;
    const float2* P = jb.P[job] + (size_t)row * 64;
    float2 a = P[l], b = P[l + 32];
    float mx = fmaxf(a.x, b.x);
    float s = a.y * exp2f(a.x - mx) + b.y * exp2f(b.x - mx);
#pragma unroll
    for (int o = 16; o; o >>= 1) {
        float m2 = __shfl_xor_sync(0xFFFFFFFFu, mx, o);
        float s2 = __shfl_xor_sync(0xFFFFFFFFu, s, o);
        float mn = fmaxf(mx, m2);
        s = fmaf(s, exp2f(mx - mn), s2 * exp2f(m2 - mn));
        mx = mn;
    }
    if (l == 0) {
        float res = -eps * LN2 * (mx + __log2f(s));
        const float* ov = jb.oldv[job];
        jb.out[job][row] = ov ? 0.5f * (ov[row] + res) : res;
    }
}

// ---------------------------------------------------------------------------
__global__ void final_reduce_kernel(float* __restrict__ out, int n) {
    __shared__ float red[256];
    float s = 0.f;
    for (int i = threadIdx.x; i < n; i += 256)
        s += (d_vec[8][i] - d_vec[10][i]) + (d_vec[9][i] - d_vec[11][i]);
    red[threadIdx.x] = s;
    __syncthreads();
    for (int o = 128; o; o >>= 1) {
        if (threadIdx.x < o) red[threadIdx.x] += red[threadIdx.x + o];
        __syncthreads();
    }
    if (threadIdx.x == 0) out[0] = red[0] / (float)n;
}

// ---------------------------------------------------------------------------
extern "C" void kernel_launch(void* const* d_in, const int* in_sizes, int n_in,
                              void* d_out, int out_size) {
    const float* gx = (const float*)d_in[0];
    const float* gy = (const float*)d_in[1];
    const float* eps = (const float*)d_in[2];
    int N = in_sizes[0] / DDIM;
    int M = in_sizes[1] / DDIM;
    int L = in_sizes[2];
    if (N > NMAX || M > NMAX) return;

    float *Cxy, *Cxx, *Cyy, *sq, *vec;
    float2 *Pr, *Pc, *Pxx, *Pyy;
    cudaGetSymbolAddress((void**)&Cxy, d_Cxy);
    cudaGetSymbolAddress((void**)&Cxx, d_Cxx);
    cudaGetSymbolAddress((void**)&Cyy, d_Cyy);
    cudaGetSymbolAddress((void**)&sq, d_sq);
    cudaGetSymbolAddress((void**)&vec, d_vec);
    cudaGetSymbolAddress((void**)&Pr, d_Pr);
    cudaGetSymbolAddress((void**)&Pc, d_Pc);
    cudaGetSymbolAddress((void**)&Pxx, d_Pxx);
    cudaGetSymbolAddress((void**)&Pyy, d_Pyy);
    float* sqx = sq;
    float* sqy = sq + NMAX;
#define V(i) (vec + (size_t)(i) * NMAX)

    float alog = -logf((float)N);
    float blog = -logf((float)M);

    // --- cost matrices (Cyx never materialized; Cxx/Cyy upper tiles only) ---
    sqnorm_kernel<<<(N + 7) / 8, 256>>>(gx, sqx, N, DDIM);
    sqnorm_kernel<<<(M + 7) / 8, 256>>>(gy, sqy, M, DDIM);

    dim3 g64(M / BM, N / BM);
    cost_gemm_kernel<<<g64, 256>>>(gx, gy, sqx, sqy, Cxy, M, DDIM, 0);
    cost_gemm_kernel<<<dim3(N / BM, N / BM), 256>>>(gx, gx, sqx, sqx, Cxx, N, DDIM, 1);
    cost_gemm_kernel<<<dim3(M / BM, M / BM), 256>>>(gy, gy, sqy, sqy, Cyy, M, DDIM, 1);

    dim3 tg(M / 128, N / 128);
    dim3 s2g(N / 8, 4);

    // --- init at eps_list[0] -> set0 ---
    tile_lse_kernel<<<tg, 256>>>(Cxy, nullptr, nullptr, alog, blog, Pr, Pc, eps, 0, M, 0);
    tile_lse_kernel<<<tg, 256>>>(Cxx, nullptr, nullptr, alog, alog, Pxx, Pxx, eps, 0, N, 1);
    tile_lse_kernel<<<tg, 256>>>(Cyy, nullptr, nullptr, blog, blog, Pyy, Pyy, eps, 0, M, 1);
    {
        S2Jobs jb;
        jb.P[0] = Pr;  jb.oldv[0] = nullptr; jb.out[0] = V(3);  // f_ba
        jb.P[1] = Pc;  jb.oldv[1] = nullptr; jb.out[1] = V(2);  // g_ab
        jb.P[2] = Pxx; jb.oldv[2] = nullptr; jb.out[2] = V(0);  // f_aa
        jb.P[3] = Pyy; jb.oldv[3] = nullptr; jb.out[3] = V(1);  // g_bb
        stage2_kernel<<<s2g, 256>>>(jb, eps, 0);
    }

    // --- Sinkhorn iterations (Jacobi updates + averaging, ping-pong) ---
    int cur = 0;
    for (int k = 0; k < L; k++) {
        int oth = cur ^ 4;
        // Cxy tile pass: rows->ft (h from g_ab), cols->gt (h from f_ba)
        tile_lse_kernel<<<tg, 256>>>(Cxy, V(cur + 3), V(cur + 2), alog, blog,
                                     Pr, Pc, eps, k, M, 0);
        tile_lse_kernel<<<tg, 256>>>(Cxx, V(cur + 0), V(cur + 0), alog, alog,
                                     Pxx, Pxx, eps, k, N, 1);
        tile_lse_kernel<<<tg, 256>>>(Cyy, V(cur + 1), V(cur + 1), blog, blog,
                                     Pyy, Pyy, eps, k, M, 1);
        S2Jobs jb;
        jb.P[0] = Pr;  jb.oldv[0] = V(cur + 3); jb.out[0] = V(oth + 3); // f_ba'
        jb.P[1] = Pc;  jb.oldv[1] = V(cur + 2); jb.out[1] = V(oth + 2); // g_ab'
        jb.P[2] = Pxx; jb.oldv[2] = V(cur + 0); jb.out[2] = V(oth + 0); // f_aa'
        jb.P[3] = Pyy; jb.oldv[3] = V(cur + 1); jb.out[3] = V(oth + 1); // g_bb'
        stage2_kernel<<<s2g, 256>>>(jb, eps, k);
        cur = oth;
    }

    // --- final extrapolation at eps_list[L-1] ---
    tile_lse_kernel<<<tg, 256>>>(Cxy, V(cur + 3), V(cur + 2), alog, blog,
                                 Pr, Pc, eps, L - 1, M, 0);
    tile_lse_kernel<<<tg, 256>>>(Cxx, V(cur + 0), V(cur + 0), alog, alog,
                                 Pxx, Pxx, eps, L - 1, N, 1);
    tile_lse_kernel<<<tg, 256>>>(Cyy, V(cur + 1), V(cur + 1), blog, blog,
                                 Pyy, Pyy, eps, L - 1, M, 1);
    {
        S2Jobs jb;
        jb.P[0] = Pr;  jb.oldv[0] = nullptr; jb.out[0] = V(8);   // f_ba_f
        jb.P[1] = Pc;  jb.oldv[1] = nullptr; jb.out[1] = V(9);   // g_ab_f
        jb.P[2] = Pxx; jb.oldv[2] = nullptr; jb.out[2] = V(10);  // f_aa_f
        jb.P[3] = Pyy; jb.oldv[3] = nullptr; jb.out[3] = V(11);  // g_bb_f
        stage2_kernel<<<s2g, 256>>>(jb, eps, L - 1);
    }

    final_reduce_kernel<<<1, 256>>>((float*)d_out, N);
#undef V
}

// round 9
// speedup vs baseline: 1.8714x; 1.0571x over previous
#include <cuda_runtime.h>
#include <math.h>
#include <stdint.h>

// ============================================================================
// Sinkhorn divergence, N=M=8192, D=64.
// Round 5: strip-streaming two-stage LSE.
//  - 64-row x 1024-col strip blocks, row state in regs across the strip,
//    col partials finalized per 128-col panel via one smem merge.
//  - Cxy: one pass yields row-LSE (ft) and col-LSE (gt).
//  - Cxx/Cyy: upper-strip reads only (half traffic), symmetry via col partials.
//  - All 3 matrices in ONE kernel launch per iteration.
// ============================================================================

#define NMAX  8192
#define DDIM  64
#define LOG2E 1.4426950408889634f
#define LN2   0.6931471805599453f
#define PW    136   // partial slots: 128 col-bands + 8 row-chunks

static __device__ float d_Cxy[(size_t)NMAX * NMAX];
static __device__ float d_Cxx[(size_t)NMAX * NMAX];   // upper tiles only
static __device__ float d_Cyy[(size_t)NMAX * NMAX];   // upper tiles only
static __device__ float d_sq[2][NMAX];
// 0 f_aa, 1 g_bb, 2 g_ab, 3 f_ba (set0); 4..7 set1; 8..11 final potentials
static __device__ float d_vec[12][NMAX];
// partial buffers, transposed: P[slot][index]
static __device__ float2 d_P[3][(size_t)PW * NMAX];

// ---------------------------------------------------------------------------
__global__ void sqnorm_kernel(const float* __restrict__ X, float* __restrict__ out,
                              int n, int d) {
    int row = blockIdx.x * (blockDim.x >> 5) + (threadIdx.x >> 5);
    int lane = threadIdx.x & 31;
    if (row >= n) return;
    float s = 0.f;
    for (int c = lane; c < d; c += 32) {
        float v = X[(size_t)row * d + c];
        s += v * v;
    }
#pragma unroll
    for (int o = 16; o; o >>= 1) s += __shfl_xor_sync(0xFFFFFFFFu, s, o);
    if (lane == 0) out[row] = s;
}

// ---------------------------------------------------------------------------
// cost GEMM: C[i][j] = max(0.5*sqa[i] + 0.5*sqb[j] - A_i.B_j, 0)
// sym=1: only 128x128 tiles bi<=bj computed/written.
// ---------------------------------------------------------------------------
#define BM 128
#define BKC 32

__global__ __launch_bounds__(256) void cost_gemm_kernel(
    const float* __restrict__ A, const float* __restrict__ B,
    const float* __restrict__ sqa, const float* __restrict__ sqb,
    float* __restrict__ C1, int nB, int d, int sym)
{
    int bj = blockIdx.x, bi = blockIdx.y;
    if (sym && bi > bj) return;

    __shared__ float As[BKC][BM + 4];
    __shared__ float Bs[BKC][BM + 4];

    int tid = threadIdx.x;
    int ti = tid & 15, tj = tid >> 4;
    int i0 = ti * 8, j0 = tj * 8;

    const float* Ab = A + (size_t)bi * BM * d;
    const float* Bb = B + (size_t)bj * BM * d;

    float acc[8][8];
#pragma unroll
    for (int a = 0; a < 8; a++)
#pragma unroll
        for (int b = 0; b < 8; b++) acc[a][b] = 0.f;

    for (int kk = 0; kk < d; kk += BKC) {
#pragma unroll
        for (int v = tid; v < 1024; v += 256) {
            int r = v >> 3, c4 = (v & 7) * 4;
            float4 a = *(const float4*)(Ab + (size_t)r * d + kk + c4);
            As[c4 + 0][r] = a.x; As[c4 + 1][r] = a.y;
            As[c4 + 2][r] = a.z; As[c4 + 3][r] = a.w;
            float4 b = *(const float4*)(Bb + (size_t)r * d + kk + c4);
            Bs[c4 + 0][r] = b.x; Bs[c4 + 1][r] = b.y;
            Bs[c4 + 2][r] = b.z; Bs[c4 + 3][r] = b.w;
        }
        __syncthreads();
#pragma unroll
        for (int k = 0; k < BKC; k++) {
            float4 a0 = *(const float4*)&As[k][i0];
            float4 a1 = *(const float4*)&As[k][i0 + 4];
            float4 b0 = *(const float4*)&Bs[k][j0];
            float4 b1 = *(const float4*)&Bs[k][j0 + 4];
            float av[8] = {a0.x, a0.y, a0.z, a0.w, a1.x, a1.y, a1.z, a1.w};
            float bv[8] = {b0.x, b0.y, b0.z, b0.w, b1.x, b1.y, b1.z, b1.w};
#pragma unroll
            for (int ii = 0; ii < 8; ii++)
#pragma unroll
                for (int jj = 0; jj < 8; jj++)
                    acc[ii][jj] += av[ii] * bv[jj];
        }
        __syncthreads();
    }

    float si[8], sj[8];
#pragma unroll
    for (int ii = 0; ii < 8; ii++) si[ii] = 0.5f * sqa[bi * BM + i0 + ii];
#pragma unroll
    for (int jj = 0; jj < 8; jj++) sj[jj] = 0.5f * sqb[bj * BM + j0 + jj];

#pragma unroll
    for (int ii = 0; ii < 8; ii++) {
        size_t off = (size_t)(bi * BM + i0 + ii) * nB + bj * BM + j0;
        float4 w0 = make_float4(
            fmaxf(si[ii] + sj[0] - acc[ii][0], 0.f),
            fmaxf(si[ii] + sj[1] - acc[ii][1], 0.f),
            fmaxf(si[ii] + sj[2] - acc[ii][2], 0.f),
            fmaxf(si[ii] + sj[3] - acc[ii][3], 0.f));
        float4 w1 = make_float4(
            fmaxf(si[ii] + sj[4] - acc[ii][4], 0.f),
            fmaxf(si[ii] + sj[5] - acc[ii][5], 0.f),
            fmaxf(si[ii] + sj[6] - acc[ii][6], 0.f),
            fmaxf(si[ii] + sj[7] - acc[ii][7], 0.f));
        *(float4*)(C1 + off) = w0;
        *(float4*)(C1 + off + 4) = w1;
    }
}

// ---------------------------------------------------------------------------
// strip kernel: 64-row x (<=1024)-col chunks over all 3 matrices in one grid.
//  mat 0 = Cxy (full), mat 1 = Cxx (cols >= 64*band), mat 2 = Cyy.
//  Per 128-col panel-pair: lane covers 8 rows x 4 cols.
//  Row LSE accumulated in regs across the chunk -> slot (nbands + chunk).
//  Col partials finalized per panel-pair -> slot band (transposed layout).
//  Symmetric matrices skip col-partial writes for own-band cols.
// ---------------------------------------------------------------------------
struct StripP {
    const float* C[3];
    float2*      P[3];
    const float* potr[3];
    const float* potc[3];
    float        lwr[3], lwc[3];
    const float* eps_list;
    int eps_idx;
    int nn, nbands, cpr, blocksXY, blocksSym;
};

__global__ __launch_bounds__(256, 2) void strip_kernel(StripP prm)
{
    int nn = prm.nn;
    int id = blockIdx.x;
    int mat, band, chunk;
    if (id < prm.blocksXY) {
        mat = 0;
        band = id / prm.cpr;
        chunk = id - band * prm.cpr;
    } else {
        id -= prm.blocksXY;
        mat = 1 + id / prm.blocksSym;
        int sid = id - (mat - 1) * prm.blocksSym;
        int b = 0;
        for (;;) {
            int nc = (prm.nbands - b + 15) >> 4;
            if (sid < nc) break;
            sid -= nc; b++;
        }
        band = b; chunk = sid;
    }
    int c0, c1;
    if (mat == 0) { c0 = chunk << 10; c1 = c0 + 1024; }
    else { c0 = (band << 6) + (chunk << 10); c1 = min(c0 + 1024, nn); }
    int row0 = band << 6;

    const float* __restrict__ C = prm.C[mat];
    float2* __restrict__ P = prm.P[mat];
    const float* potr = prm.potr[mat];
    const float* potc = prm.potc[mat];

    float eps = prm.eps_list[prm.eps_idx];
    float ie2 = LOG2E / eps;
    float lwr2 = prm.lwr[mat] * LOG2E;
    float lwc2 = prm.lwc[mat] * LOG2E;

    int w = threadIdx.x >> 5, l = threadIdx.x & 31;
    int rbase = row0 + w * 8;

    float har[8];
#pragma unroll
    for (int r = 0; r < 8; r++)
        har[r] = potr ? fmaf(potr[rbase + r], ie2, lwr2) : lwr2;

    float rmx[8], rs[8];
#pragma unroll
    for (int r = 0; r < 8; r++) { rmx[r] = -3.4e38f; rs[r] = 0.f; }

    __shared__ float2 smc[8][128];
    const float* Cb = C + (size_t)rbase * nn;

    int pc0 = c0;
    // -------- 128-col panel pairs --------
    for (; pc0 + 128 <= c1; pc0 += 128) {
        int j = pc0 + l * 4;
        float4 u[8];
#pragma unroll
        for (int r = 0; r < 8; r++)
            u[r] = *(const float4*)(Cb + (size_t)r * nn + j);
        float4 hc;
        if (potc) {
            float4 p = *(const float4*)(potc + j);
            hc.x = fmaf(p.x, ie2, lwc2); hc.y = fmaf(p.y, ie2, lwc2);
            hc.z = fmaf(p.z, ie2, lwc2); hc.w = fmaf(p.w, ie2, lwc2);
        } else hc = make_float4(lwc2, lwc2, lwc2, lwc2);

        float cm0 = -3.4e38f, cm1 = -3.4e38f, cm2 = -3.4e38f, cm3 = -3.4e38f;
#pragma unroll
        for (int r = 0; r < 8; r++) {
            u[r].x *= -ie2; u[r].y *= -ie2; u[r].z *= -ie2; u[r].w *= -ie2;
            float v0 = u[r].x + hc.x, v1 = u[r].y + hc.y;
            float v2 = u[r].z + hc.z, v3 = u[r].w + hc.w;
            float m4 = fmaxf(fmaxf(v0, v1), fmaxf(v2, v3));
            float mn = fmaxf(rmx[r], m4);
            float e = exp2f(v0 - mn) + exp2f(v1 - mn)
                    + exp2f(v2 - mn) + exp2f(v3 - mn);
            rs[r] = fmaf(rs[r], exp2f(rmx[r] - mn), e);
            rmx[r] = mn;
            float a = har[r];
            cm0 = fmaxf(cm0, u[r].x + a); cm1 = fmaxf(cm1, u[r].y + a);
            cm2 = fmaxf(cm2, u[r].z + a); cm3 = fmaxf(cm3, u[r].w + a);
        }
        float cs0 = 0.f, cs1 = 0.f, cs2 = 0.f, cs3 = 0.f;
#pragma unroll
        for (int r = 0; r < 8; r++) {
            float a = har[r];
            cs0 += exp2f(u[r].x + a - cm0);
            cs1 += exp2f(u[r].y + a - cm1);
            cs2 += exp2f(u[r].z + a - cm2);
            cs3 += exp2f(u[r].w + a - cm3);
        }
        smc[w][l * 4 + 0] = make_float2(cm0, cs0);
        smc[w][l * 4 + 1] = make_float2(cm1, cs1);
        smc[w][l * 4 + 2] = make_float2(cm2, cs2);
        smc[w][l * 4 + 3] = make_float2(cm3, cs3);
        __syncthreads();
        if (threadIdx.x < 128) {
            int cc = threadIdx.x;
            float2 a = smc[0][cc];
            float m = a.x, s = a.y;
#pragma unroll
            for (int ww = 1; ww < 8; ww++) {
                float2 b = smc[ww][cc];
                float mn = fmaxf(m, b.x);
                s = fmaf(s, exp2f(m - mn), b.y * exp2f(b.x - mn));
                m = mn;
            }
            int jj = pc0 + cc;
            if (!(mat && ((jj >> 6) == band)))
                P[(size_t)band * nn + jj] = make_float2(m, s);
        }
        __syncthreads();
    }
    // -------- 64-col tail panel --------
    if (pc0 < c1) {
        int j = pc0 + l * 2;
        float2 u2[8];
#pragma unroll
        for (int r = 0; r < 8; r++)
            u2[r] = *(const float2*)(Cb + (size_t)r * nn + j);
        float h0 = lwc2, h1 = lwc2;
        if (potc) {
            h0 = fmaf(potc[j], ie2, lwc2);
            h1 = fmaf(potc[j + 1], ie2, lwc2);
        }
        float cm0 = -3.4e38f, cm1 = -3.4e38f;
#pragma unroll
        for (int r = 0; r < 8; r++) {
            u2[r].x *= -ie2; u2[r].y *= -ie2;
            float v0 = u2[r].x + h0, v1 = u2[r].y + h1;
            float m2v = fmaxf(v0, v1);
            float mn = fmaxf(rmx[r], m2v);
            float e = exp2f(v0 - mn) + exp2f(v1 - mn);
            rs[r] = fmaf(rs[r], exp2f(rmx[r] - mn), e);
            rmx[r] = mn;
            float a = har[r];
            cm0 = fmaxf(cm0, u2[r].x + a);
            cm1 = fmaxf(cm1, u2[r].y + a);
        }
        float cs0 = 0.f, cs1 = 0.f;
#pragma unroll
        for (int r = 0; r < 8; r++) {
            float a = har[r];
            cs0 += exp2f(u2[r].x + a - cm0);
            cs1 += exp2f(u2[r].y + a - cm1);
        }
        smc[w][l * 2 + 0] = make_float2(cm0, cs0);
        smc[w][l * 2 + 1] = make_float2(cm1, cs1);
        __syncthreads();
        if (threadIdx.x < 64) {
            int cc = threadIdx.x;
            float2 a = smc[0][cc];
            float m = a.x, s = a.y;
#pragma unroll
            for (int ww = 1; ww < 8; ww++) {
                float2 b = smc[ww][cc];
                float mn = fmaxf(m, b.x);
                s = fmaf(s, exp2f(m - mn), b.y * exp2f(b.x - mn));
                m = mn;
            }
            int jj = pc0 + cc;
            if (!(mat && ((jj >> 6) == band)))
                P[(size_t)band * nn + jj] = make_float2(m, s);
        }
        __syncthreads();
    }
    // -------- row partial output (once per chunk) --------
#pragma unroll
    for (int r = 0; r < 8; r++) {
        float m = rmx[r], s = rs[r];
#pragma unroll
        for (int o = 16; o; o >>= 1) {
            float m2 = __shfl_xor_sync(0xFFFFFFFFu, m, o);
            float s2 = __shfl_xor_sync(0xFFFFFFFFu, s, o);
            float mn = fmaxf(m, m2);
            s = fmaf(s, exp2f(m - mn), s2 * exp2f(m2 - mn));
            m = mn;
        }
        if (l == 0)
            P[(size_t)(prm.nbands + chunk) * nn + rbase + r] = make_float2(m, s);
    }
}

// ---------------------------------------------------------------------------
// stage 2: thread-per-row merge of partials (coalesced across warp).
//  colLim >= 0: fixed count of col-band slots; -1: band(row) (symmetric).
//  chLim  >= 0: fixed count of row-chunk slots; -1: ceil((nbands-band)/16).
// ---------------------------------------------------------------------------
struct S2J {
    const float2* P[4];
    const float*  oldv[4];
    float*        out[4];
    int colLim[4];
    int chLim[4];
};

__global__ __launch_bounds__(256) void stage2_kernel(
    S2J jb, const float* __restrict__ eps_list, int eps_idx, int nn, int nbands)
{
    int job = blockIdx.y;
    int row = blockIdx.x * 256 + threadIdx.x;
    float eps = eps_list[eps_idx];
    const float2* __restrict__ P = jb.P[job];
    int band = row >> 6;
    int cl = jb.colLim[job]; if (cl < 0) cl = band;
    int ch = jb.chLim[job];  if (ch < 0) ch = (nbands - band + 15) >> 4;

    float mx = -3.4e38f, s = 0.f;
    for (int t = 0; t < cl; t++) {
        float2 p = P[(size_t)t * nn + row];
        float mn = fmaxf(mx, p.x);
        s = fmaf(s, exp2f(mx - mn), p.y * exp2f(p.x - mn));
        mx = mn;
    }
    for (int t = 0; t < ch; t++) {
        float2 p = P[(size_t)(nbands + t) * nn + row];
        float mn = fmaxf(mx, p.x);
        s = fmaf(s, exp2f(mx - mn), p.y * exp2f(p.x - mn));
        mx = mn;
    }
    float res = -eps * LN2 * (mx + __log2f(s));
    const float* ov = jb.oldv[job];
    jb.out[job][row] = ov ? 0.5f * (ov[row] + res) : res;
}

// ---------------------------------------------------------------------------
__global__ void final_reduce_kernel(float* __restrict__ out, int n) {
    __shared__ float red[256];
    float s = 0.f;
    for (int i = threadIdx.x; i < n; i += 256)
        s += (d_vec[8][i] - d_vec[10][i]) + (d_vec[9][i] - d_vec[11][i]);
    red[threadIdx.x] = s;
    __syncthreads();
    for (int o = 128; o; o >>= 1) {
        if (threadIdx.x < o) red[threadIdx.x] += red[threadIdx.x + o];
        __syncthreads();
    }
    if (threadIdx.x == 0) out[0] = red[0] / (float)n;
}

// ---------------------------------------------------------------------------
extern "C" void kernel_launch(void* const* d_in, const int* in_sizes, int n_in,
                              void* d_out, int out_size) {
    const float* gx = (const float*)d_in[0];
    const float* gy = (const float*)d_in[1];
    const float* eps = (const float*)d_in[2];
    int N = in_sizes[0] / DDIM;
    int M = in_sizes[1] / DDIM;
    int L = in_sizes[2];
    if (N > NMAX || M > NMAX || N != M) return;
    int nn = N;

    float *Cxy, *Cxx, *Cyy, *sq, *vec;
    float2* Pbase;
    cudaGetSymbolAddress((void**)&Cxy, d_Cxy);
    cudaGetSymbolAddress((void**)&Cxx, d_Cxx);
    cudaGetSymbolAddress((void**)&Cyy, d_Cyy);
    cudaGetSymbolAddress((void**)&sq, d_sq);
    cudaGetSymbolAddress((void**)&vec, d_vec);
    cudaGetSymbolAddress((void**)&Pbase, d_P);
    float* sqx = sq;
    float* sqy = sq + NMAX;
    float2* P0 = Pbase;
    float2* P1 = Pbase + (size_t)PW * NMAX;
    float2* P2 = Pbase + 2 * (size_t)PW * NMAX;
#define V(i) (vec + (size_t)(i) * NMAX)

    float alog = -logf((float)N);
    float blog = -logf((float)M);

    // --- cost matrices ---
    sqnorm_kernel<<<(N + 7) / 8, 256>>>(gx, sqx, N, DDIM);
    sqnorm_kernel<<<(M + 7) / 8, 256>>>(gy, sqy, M, DDIM);
    cost_gemm_kernel<<<dim3(M / BM, N / BM), 256>>>(gx, gy, sqx, sqy, Cxy, M, DDIM, 0);
    cost_gemm_kernel<<<dim3(N / BM, N / BM), 256>>>(gx, gx, sqx, sqx, Cxx, N, DDIM, 1);
    cost_gemm_kernel<<<dim3(M / BM, M / BM), 256>>>(gy, gy, sqy, sqy, Cyy, M, DDIM, 1);

    int nbands = nn / 64;               // 128
    int cpr = nn / 1024;                // 8
    int blocksXY = nbands * cpr;        // 1024
    int S = 0;
    for (int b = 0; b < nbands; b++) S += (nbands - b + 15) >> 4;
    int totalBlocks = blocksXY + 2 * S;

    StripP sp;
    sp.C[0] = Cxy; sp.C[1] = Cxx; sp.C[2] = Cyy;
    sp.P[0] = P0;  sp.P[1] = P1;  sp.P[2] = P2;
    sp.lwr[0] = alog; sp.lwc[0] = blog;
    sp.lwr[1] = alog; sp.lwc[1] = alog;
    sp.lwr[2] = blog; sp.lwc[2] = blog;
    sp.eps_list = eps;
    sp.nn = nn; sp.nbands = nbands; sp.cpr = cpr;
    sp.blocksXY = blocksXY; sp.blocksSym = S;

    S2J jb;
    jb.P[0] = P0; jb.colLim[0] = 0;      jb.chLim[0] = cpr;  // xy rows -> f_ba
    jb.P[1] = P0; jb.colLim[1] = nbands; jb.chLim[1] = 0;    // xy cols -> g_ab
    jb.P[2] = P1; jb.colLim[2] = -1;     jb.chLim[2] = -1;   // xx -> f_aa
    jb.P[3] = P2; jb.colLim[3] = -1;     jb.chLim[3] = -1;   // yy -> g_bb

    dim3 s2g(nn / 256, 4);

    // --- init at eps_list[0] (no potentials, no blend) -> set0 ---
    sp.eps_idx = 0;
    sp.potr[0] = nullptr; sp.potc[0] = nullptr;
    sp.potr[1] = nullptr; sp.potc[1] = nullptr;
    sp.potr[2] = nullptr; sp.potc[2] = nullptr;
    strip_kernel<<<totalBlocks, 256>>>(sp);
    jb.oldv[0] = nullptr; jb.out[0] = V(3);
    jb.oldv[1] = nullptr; jb.out[1] = V(2);
    jb.oldv[2] = nullptr; jb.out[2] = V(0);
    jb.oldv[3] = nullptr; jb.out[3] = V(1);
    stage2_kernel<<<s2g, 256>>>(jb, eps, 0, nn, nbands);

    // --- Sinkhorn iterations (ping-pong with blended epilogue) ---
    int cur = 0;
    for (int k = 0; k < L; k++) {
        int oth = cur ^ 4;
        sp.eps_idx = k;
        sp.potr[0] = V(cur + 3); sp.potc[0] = V(cur + 2);  // f_ba rows, g_ab cols
        sp.potr[1] = V(cur + 0); sp.potc[1] = V(cur + 0);  // f_aa
        sp.potr[2] = V(cur + 1); sp.potc[2] = V(cur + 1);  // g_bb
        strip_kernel<<<totalBlocks, 256>>>(sp);
        jb.oldv[0] = V(cur + 3); jb.out[0] = V(oth + 3);   // f_ba'
        jb.oldv[1] = V(cur + 2); jb.out[1] = V(oth + 2);   // g_ab'
        jb.oldv[2] = V(cur + 0); jb.out[2] = V(oth + 0);   // f_aa'
        jb.oldv[3] = V(cur + 1); jb.out[3] = V(oth + 1);   // g_bb'
        stage2_kernel<<<s2g, 256>>>(jb, eps, k, nn, nbands);
        cur = oth;
    }

    // --- final extrapolation at eps_list[L-1] (no blend) ---
    sp.eps_idx = L - 1;
    sp.potr[0] = V(cur + 3); sp.potc[0] = V(cur + 2);
    sp.potr[1] = V(cur + 0); sp.potc[1] = V(cur + 0);
    sp.potr[2] = V(cur + 1); sp.potc[2] = V(cur + 1);
    strip_kernel<<<totalBlocks, 256>>>(sp);
    jb.oldv[0] = nullptr; jb.out[0] = V(8);    // f_ba_f
    jb.oldv[1] = nullptr; jb.out[1] = V(9);    // g_ab_f
    jb.oldv[2] = nullptr; jb.out[2] = V(10);   // f_aa_f
    jb.oldv[3] = nullptr; jb.out[3] = V(11);   // g_bb_f
    stage2_kernel<<<s2g, 256>>>(jb, eps, L - 1, nn, nbands);

    final_reduce_kernel<<<1, 256>>>((float*)d_out, N);
#undef V
}

// round 13
// speedup vs baseline: 1.9839x; 1.0602x over previous
#include <cuda_runtime.h>
#include <math.h>
#include <stdint.h>

// ============================================================================
// Sinkhorn divergence, N=M=8192, D=64.
// Round 6: strip-streaming two-stage LSE with
//  - guaranteed single-instruction EX2 via inline PTX (no fast-math dependence)
//  - warp-uniform skip votes in both row-LSE and col-sum passes
// ============================================================================

#define NMAX  8192
#define DDIM  64
#define LOG2E 1.4426950408889634f
#define LN2   0.6931471805599453f
#define PW    136   // partial slots: 128 col-bands + 8 row-chunks

static __device__ float d_Cxy[(size_t)NMAX * NMAX];
static __device__ float d_Cxx[(size_t)NMAX * NMAX];   // upper tiles only
static __device__ float d_Cyy[(size_t)NMAX * NMAX];   // upper tiles only
static __device__ float d_sq[2][NMAX];
// 0 f_aa, 1 g_bb, 2 g_ab, 3 f_ba (set0); 4..7 set1; 8..11 final potentials
static __device__ float d_vec[12][NMAX];
// partial buffers, transposed: P[slot][index]
static __device__ float2 d_P[3][(size_t)PW * NMAX];

// single-instruction exponential (args are always <= 0 here)
__device__ __forceinline__ float ex2f(float x) {
    float y;
    asm("ex2.approx.ftz.f32 %0, %1;" : "=f"(y) : "f"(x));
    return y;
}
__device__ __forceinline__ float lg2f(float x) {
    float y;
    asm("lg2.approx.ftz.f32 %0, %1;" : "=f"(y) : "f"(x));
    return y;
}

// ---------------------------------------------------------------------------
__global__ void sqnorm_kernel(const float* __restrict__ X, float* __restrict__ out,
                              int n, int d) {
    int row = blockIdx.x * (blockDim.x >> 5) + (threadIdx.x >> 5);
    int lane = threadIdx.x & 31;
    if (row >= n) return;
    float s = 0.f;
    for (int c = lane; c < d; c += 32) {
        float v = X[(size_t)row * d + c];
        s += v * v;
    }
#pragma unroll
    for (int o = 16; o; o >>= 1) s += __shfl_xor_sync(0xFFFFFFFFu, s, o);
    if (lane == 0) out[row] = s;
}

// ---------------------------------------------------------------------------
// cost GEMM: C[i][j] = max(0.5*sqa[i] + 0.5*sqb[j] - A_i.B_j, 0)
// sym=1: only 128x128 tiles bi<=bj computed/written.
// ---------------------------------------------------------------------------
#define BM 128
#define BKC 32

__global__ __launch_bounds__(256) void cost_gemm_kernel(
    const float* __restrict__ A, const float* __restrict__ B,
    const float* __restrict__ sqa, const float* __restrict__ sqb,
    float* __restrict__ C1, int nB, int d, int sym)
{
    int bj = blockIdx.x, bi = blockIdx.y;
    if (sym && bi > bj) return;

    __shared__ float As[BKC][BM + 4];
    __shared__ float Bs[BKC][BM + 4];

    int tid = threadIdx.x;
    int ti = tid & 15, tj = tid >> 4;
    int i0 = ti * 8, j0 = tj * 8;

    const float* Ab = A + (size_t)bi * BM * d;
    const float* Bb = B + (size_t)bj * BM * d;

    float acc[8][8];
#pragma unroll
    for (int a = 0; a < 8; a++)
#pragma unroll
        for (int b = 0; b < 8; b++) acc[a][b] = 0.f;

    for (int kk = 0; kk < d; kk += BKC) {
#pragma unroll
        for (int v = tid; v < 1024; v += 256) {
            int r = v >> 3, c4 = (v & 7) * 4;
            float4 a = *(const float4*)(Ab + (size_t)r * d + kk + c4);
            As[c4 + 0][r] = a.x; As[c4 + 1][r] = a.y;
            As[c4 + 2][r] = a.z; As[c4 + 3][r] = a.w;
            float4 b = *(const float4*)(Bb + (size_t)r * d + kk + c4);
            Bs[c4 + 0][r] = b.x; Bs[c4 + 1][r] = b.y;
            Bs[c4 + 2][r] = b.z; Bs[c4 + 3][r] = b.w;
        }
        __syncthreads();
#pragma unroll
        for (int k = 0; k < BKC; k++) {
            float4 a0 = *(const float4*)&As[k][i0];
            float4 a1 = *(const float4*)&As[k][i0 + 4];
            float4 b0 = *(const float4*)&Bs[k][j0];
            float4 b1 = *(const float4*)&Bs[k][j0 + 4];
            float av[8] = {a0.x, a0.y, a0.z, a0.w, a1.x, a1.y, a1.z, a1.w};
            float bv[8] = {b0.x, b0.y, b0.z, b0.w, b1.x, b1.y, b1.z, b1.w};
#pragma unroll
            for (int ii = 0; ii < 8; ii++)
#pragma unroll
                for (int jj = 0; jj < 8; jj++)
                    acc[ii][jj] += av[ii] * bv[jj];
        }
        __syncthreads();
    }

    float si[8], sj[8];
#pragma unroll
    for (int ii = 0; ii < 8; ii++) si[ii] = 0.5f * sqa[bi * BM + i0 + ii];
#pragma unroll
    for (int jj = 0; jj < 8; jj++) sj[jj] = 0.5f * sqb[bj * BM + j0 + jj];

#pragma unroll
    for (int ii = 0; ii < 8; ii++) {
        size_t off = (size_t)(bi * BM + i0 + ii) * nB + bj * BM + j0;
        float4 w0 = make_float4(
            fmaxf(si[ii] + sj[0] - acc[ii][0], 0.f),
            fmaxf(si[ii] + sj[1] - acc[ii][1], 0.f),
            fmaxf(si[ii] + sj[2] - acc[ii][2], 0.f),
            fmaxf(si[ii] + sj[3] - acc[ii][3], 0.f));
        float4 w1 = make_float4(
            fmaxf(si[ii] + sj[4] - acc[ii][4], 0.f),
            fmaxf(si[ii] + sj[5] - acc[ii][5], 0.f),
            fmaxf(si[ii] + sj[6] - acc[ii][6], 0.f),
            fmaxf(si[ii] + sj[7] - acc[ii][7], 0.f));
        *(float4*)(C1 + off) = w0;
        *(float4*)(C1 + off + 4) = w1;
    }
}

// ---------------------------------------------------------------------------
// strip kernel: 64-row x (<=1024)-col chunks over all 3 matrices in one grid.
// Row LSE in regs across the chunk; col partials per 128-col panel via smem.
// Warp-uniform skip votes avoid EX2 issue for irrelevant panels/rows.
// ---------------------------------------------------------------------------
struct StripP {
    const float* C[3];
    float2*      P[3];
    const float* potr[3];
    const float* potc[3];
    float        lwr[3], lwc[3];
    const float* eps_list;
    int eps_idx;
    int nn, nbands, cpr, blocksXY, blocksSym;
};

__global__ __launch_bounds__(256, 2) void strip_kernel(StripP prm)
{
    int nn = prm.nn;
    int id = blockIdx.x;
    int mat, band, chunk;
    if (id < prm.blocksXY) {
        mat = 0;
        band = id / prm.cpr;
        chunk = id - band * prm.cpr;
    } else {
        id -= prm.blocksXY;
        mat = 1 + id / prm.blocksSym;
        int sid = id - (mat - 1) * prm.blocksSym;
        int b = 0;
        for (;;) {
            int nc = (prm.nbands - b + 15) >> 4;
            if (sid < nc) break;
            sid -= nc; b++;
        }
        band = b; chunk = sid;
    }
    int c0, c1;
    if (mat == 0) { c0 = chunk << 10; c1 = c0 + 1024; }
    else { c0 = (band << 6) + (chunk << 10); c1 = min(c0 + 1024, nn); }
    int row0 = band << 6;

    const float* __restrict__ C = prm.C[mat];
    float2* __restrict__ P = prm.P[mat];
    const float* potr = prm.potr[mat];
    const float* potc = prm.potc[mat];

    float eps = prm.eps_list[prm.eps_idx];
    float ie2 = LOG2E / eps;
    float lwr2 = prm.lwr[mat] * LOG2E;
    float lwc2 = prm.lwc[mat] * LOG2E;

    int w = threadIdx.x >> 5, l = threadIdx.x & 31;
    int rbase = row0 + w * 8;

    float har[8];
#pragma unroll
    for (int r = 0; r < 8; r++)
        har[r] = potr ? fmaf(potr[rbase + r], ie2, lwr2) : lwr2;

    float rmx[8], rs[8];
#pragma unroll
    for (int r = 0; r < 8; r++) { rmx[r] = -3.4e38f; rs[r] = 0.f; }

    __shared__ float2 smc[8][128];
    const float* Cb = C + (size_t)rbase * nn;

    int pc0 = c0;
    // -------- 128-col panel pairs --------
    for (; pc0 + 128 <= c1; pc0 += 128) {
        int j = pc0 + l * 4;
        float4 u[8];
#pragma unroll
        for (int r = 0; r < 8; r++)
            u[r] = *(const float4*)(Cb + (size_t)r * nn + j);
        float4 hc;
        if (potc) {
            float4 p = *(const float4*)(potc + j);
            hc.x = fmaf(p.x, ie2, lwc2); hc.y = fmaf(p.y, ie2, lwc2);
            hc.z = fmaf(p.z, ie2, lwc2); hc.w = fmaf(p.w, ie2, lwc2);
        } else hc = make_float4(lwc2, lwc2, lwc2, lwc2);

        float cm0 = -3.4e38f, cm1 = -3.4e38f, cm2 = -3.4e38f, cm3 = -3.4e38f;
#pragma unroll
        for (int r = 0; r < 8; r++) {
            u[r].x *= -ie2; u[r].y *= -ie2; u[r].z *= -ie2; u[r].w *= -ie2;
            float v0 = u[r].x + hc.x, v1 = u[r].y + hc.y;
            float v2 = u[r].z + hc.z, v3 = u[r].w + hc.w;
            float m4 = fmaxf(fmaxf(v0, v1), fmaxf(v2, v3));
            // warp-uniform vote: does any lane contribute to row r's LSE?
            if (__any_sync(0xFFFFFFFFu, m4 > rmx[r] - 24.f)) {
                float mn = fmaxf(rmx[r], m4);
                float e = ex2f(v0 - mn) + ex2f(v1 - mn)
                        + ex2f(v2 - mn) + ex2f(v3 - mn);
                rs[r] = fmaf(rs[r], ex2f(rmx[r] - mn), e);
                rmx[r] = mn;
            }
            float a = har[r];
            cm0 = fmaxf(cm0, u[r].x + a); cm1 = fmaxf(cm1, u[r].y + a);
            cm2 = fmaxf(cm2, u[r].z + a); cm3 = fmaxf(cm3, u[r].w + a);
        }
        float cs0 = 0.f, cs1 = 0.f, cs2 = 0.f, cs3 = 0.f;
#pragma unroll
        for (int r = 0; r < 8; r++) {
            float a = har[r];
            float w0 = u[r].x + a - cm0, w1 = u[r].y + a - cm1;
            float w2 = u[r].z + a - cm2, w3 = u[r].w + a - cm3;
            float m4c = fmaxf(fmaxf(w0, w1), fmaxf(w2, w3));
            // warp-uniform vote: does row r contribute to any col partial?
            if (__any_sync(0xFFFFFFFFu, m4c > -24.f)) {
                cs0 += ex2f(w0); cs1 += ex2f(w1);
                cs2 += ex2f(w2); cs3 += ex2f(w3);
            }
        }
        smc[w][l * 4 + 0] = make_float2(cm0, cs0);
        smc[w][l * 4 + 1] = make_float2(cm1, cs1);
        smc[w][l * 4 + 2] = make_float2(cm2, cs2);
        smc[w][l * 4 + 3] = make_float2(cm3, cs3);
        __syncthreads();
        if (threadIdx.x < 128) {
            int cc = threadIdx.x;
            float2 a = smc[0][cc];
            float m = a.x, s = a.y;
#pragma unroll
            for (int ww = 1; ww < 8; ww++) {
                float2 b = smc[ww][cc];
                float mn = fmaxf(m, b.x);
                s = fmaf(s, ex2f(m - mn), b.y * ex2f(b.x - mn));
                m = mn;
            }
            int jj = pc0 + cc;
            if (!(mat && ((jj >> 6) == band)))
                P[(size_t)band * nn + jj] = make_float2(m, s);
        }
        __syncthreads();
    }
    // -------- 64-col tail panel --------
    if (pc0 < c1) {
        int j = pc0 + l * 2;
        float2 u2[8];
#pragma unroll
        for (int r = 0; r < 8; r++)
            u2[r] = *(const float2*)(Cb + (size_t)r * nn + j);
        float h0 = lwc2, h1 = lwc2;
        if (potc) {
            h0 = fmaf(potc[j], ie2, lwc2);
            h1 = fmaf(potc[j + 1], ie2, lwc2);
        }
        float cm0 = -3.4e38f, cm1 = -3.4e38f;
#pragma unroll
        for (int r = 0; r < 8; r++) {
            u2[r].x *= -ie2; u2[r].y *= -ie2;
            float v0 = u2[r].x + h0, v1 = u2[r].y + h1;
            float m2v = fmaxf(v0, v1);
            if (__any_sync(0xFFFFFFFFu, m2v > rmx[r] - 24.f)) {
                float mn = fmaxf(rmx[r], m2v);
                float e = ex2f(v0 - mn) + ex2f(v1 - mn);
                rs[r] = fmaf(rs[r], ex2f(rmx[r] - mn), e);
                rmx[r] = mn;
            }
            float a = har[r];
            cm0 = fmaxf(cm0, u2[r].x + a);
            cm1 = fmaxf(cm1, u2[r].y + a);
        }
        float cs0 = 0.f, cs1 = 0.f;
#pragma unroll
        for (int r = 0; r < 8; r++) {
            float a = har[r];
            float w0 = u2[r].x + a - cm0, w1 = u2[r].y + a - cm1;
            float m2c = fmaxf(w0, w1);
            if (__any_sync(0xFFFFFFFFu, m2c > -24.f)) {
                cs0 += ex2f(w0); cs1 += ex2f(w1);
            }
        }
        smc[w][l * 2 + 0] = make_float2(cm0, cs0);
        smc[w][l * 2 + 1] = make_float2(cm1, cs1);
        __syncthreads();
        if (threadIdx.x < 64) {
            int cc = threadIdx.x;
            float2 a = smc[0][cc];
            float m = a.x, s = a.y;
#pragma unroll
            for (int ww = 1; ww < 8; ww++) {
                float2 b = smc[ww][cc];
                float mn = fmaxf(m, b.x);
                s = fmaf(s, ex2f(m - mn), b.y * ex2f(b.x - mn));
                m = mn;
            }
            int jj = pc0 + cc;
            if (!(mat && ((jj >> 6) == band)))
                P[(size_t)band * nn + jj] = make_float2(m, s);
        }
        __syncthreads();
    }
    // -------- row partial output (once per chunk) --------
#pragma unroll
    for (int r = 0; r < 8; r++) {
        float m = rmx[r], s = rs[r];
#pragma unroll
        for (int o = 16; o; o >>= 1) {
            float m2 = __shfl_xor_sync(0xFFFFFFFFu, m, o);
            float s2 = __shfl_xor_sync(0xFFFFFFFFu, s, o);
            float mn = fmaxf(m, m2);
            s = fmaf(s, ex2f(m - mn), s2 * ex2f(m2 - mn));
            m = mn;
        }
        if (l == 0)
            P[(size_t)(prm.nbands + chunk) * nn + rbase + r] = make_float2(m, s);
    }
}

// ---------------------------------------------------------------------------
// stage 2: thread-per-row merge of partials (coalesced across warp).
// ---------------------------------------------------------------------------
struct S2J {
    const float2* P[4];
    const float*  oldv[4];
    float*        out[4];
    int colLim[4];
    int chLim[4];
};

__global__ __launch_bounds__(256) void stage2_kernel(
    S2J jb, const float* __restrict__ eps_list, int eps_idx, int nn, int nbands)
{
    int job = blockIdx.y;
    int row = blockIdx.x * 256 + threadIdx.x;
    float eps = eps_list[eps_idx];
    const float2* __restrict__ P = jb.P[job];
    int band = row >> 6;
    int cl = jb.colLim[job]; if (cl < 0) cl = band;
    int ch = jb.chLim[job];  if (ch < 0) ch = (nbands - band + 15) >> 4;

    float mx = -3.4e38f, s = 0.f;
    for (int t = 0; t < cl; t++) {
        float2 p = P[(size_t)t * nn + row];
        float mn = fmaxf(mx, p.x);
        s = fmaf(s, ex2f(mx - mn), p.y * ex2f(p.x - mn));
        mx = mn;
    }
    for (int t = 0; t < ch; t++) {
        float2 p = P[(size_t)(nbands + t) * nn + row];
        float mn = fmaxf(mx, p.x);
        s = fmaf(s, ex2f(mx - mn), p.y * ex2f(p.x - mn));
        mx = mn;
    }
    float res = -eps * LN2 * (mx + lg2f(s));
    const float* ov = jb.oldv[job];
    jb.out[job][row] = ov ? 0.5f * (ov[row] + res) : res;
}

// ---------------------------------------------------------------------------
__global__ void final_reduce_kernel(float* __restrict__ out, int n) {
    __shared__ float red[256];
    float s = 0.f;
    for (int i = threadIdx.x; i < n; i += 256)
        s += (d_vec[8][i] - d_vec[10][i]) + (d_vec[9][i] - d_vec[11][i]);
    red[threadIdx.x] = s;
    __syncthreads();
    for (int o = 128; o; o >>= 1) {
        if (threadIdx.x < o) red[threadIdx.x] += red[threadIdx.x + o];
        __syncthreads();
    }
    if (threadIdx.x == 0) out[0] = red[0] / (float)n;
}

// ---------------------------------------------------------------------------
extern "C" void kernel_launch(void* const* d_in, const int* in_sizes, int n_in,
                              void* d_out, int out_size) {
    const float* gx = (const float*)d_in[0];
    const float* gy = (const float*)d_in[1];
    const float* eps = (const float*)d_in[2];
    int N = in_sizes[0] / DDIM;
    int M = in_sizes[1] / DDIM;
    int L = in_sizes[2];
    if (N > NMAX || M > NMAX || N != M) return;
    int nn = N;

    float *Cxy, *Cxx, *Cyy, *sq, *vec;
    float2* Pbase;
    cudaGetSymbolAddress((void**)&Cxy, d_Cxy);
    cudaGetSymbolAddress((void**)&Cxx, d_Cxx);
    cudaGetSymbolAddress((void**)&Cyy, d_Cyy);
    cudaGetSymbolAddress((void**)&sq, d_sq);
    cudaGetSymbolAddress((void**)&vec, d_vec);
    cudaGetSymbolAddress((void**)&Pbase, d_P);
    float* sqx = sq;
    float* sqy = sq + NMAX;
    float2* P0 = Pbase;
    float2* P1 = Pbase + (size_t)PW * NMAX;
    float2* P2 = Pbase + 2 * (size_t)PW * NMAX;
#define V(i) (vec + (size_t)(i) * NMAX)

    float alog = -logf((float)N);
    float blog = -logf((float)M);

    // --- cost matrices ---
    sqnorm_kernel<<<(N + 7) / 8, 256>>>(gx, sqx, N, DDIM);
    sqnorm_kernel<<<(M + 7) / 8, 256>>>(gy, sqy, M, DDIM);
    cost_gemm_kernel<<<dim3(M / BM, N / BM), 256>>>(gx, gy, sqx, sqy, Cxy, M, DDIM, 0);
    cost_gemm_kernel<<<dim3(N / BM, N / BM), 256>>>(gx, gx, sqx, sqx, Cxx, N, DDIM, 1);
    cost_gemm_kernel<<<dim3(M / BM, M / BM), 256>>>(gy, gy, sqy, sqy, Cyy, M, DDIM, 1);

    int nbands = nn / 64;               // 128
    int cpr = nn / 1024;                // 8
    int blocksXY = nbands * cpr;        // 1024
    int S = 0;
    for (int b = 0; b < nbands; b++) S += (nbands - b + 15) >> 4;
    int totalBlocks = blocksXY + 2 * S;

    StripP sp;
    sp.C[0] = Cxy; sp.C[1] = Cxx; sp.C[2] = Cyy;
    sp.P[0] = P0;  sp.P[1] = P1;  sp.P[2] = P2;
    sp.lwr[0] = alog; sp.lwc[0] = blog;
    sp.lwr[1] = alog; sp.lwc[1] = alog;
    sp.lwr[2] = blog; sp.lwc[2] = blog;
    sp.eps_list = eps;
    sp.nn = nn; sp.nbands = nbands; sp.cpr = cpr;
    sp.blocksXY = blocksXY; sp.blocksSym = S;

    S2J jb;
    jb.P[0] = P0; jb.colLim[0] = 0;      jb.chLim[0] = cpr;  // xy rows -> f_ba
    jb.P[1] = P0; jb.colLim[1] = nbands; jb.chLim[1] = 0;    // xy cols -> g_ab
    jb.P[2] = P1; jb.colLim[2] = -1;     jb.chLim[2] = -1;   // xx -> f_aa
    jb.P[3] = P2; jb.colLim[3] = -1;     jb.chLim[3] = -1;   // yy -> g_bb

    dim3 s2g(nn / 256, 4);

    // --- init at eps_list[0] -> set0 ---
    sp.eps_idx = 0;
    sp.potr[0] = nullptr; sp.potc[0] = nullptr;
    sp.potr[1] = nullptr; sp.potc[1] = nullptr;
    sp.potr[2] = nullptr; sp.potc[2] = nullptr;
    strip_kernel<<<totalBlocks, 256>>>(sp);
    jb.oldv[0] = nullptr; jb.out[0] = V(3);
    jb.oldv[1] = nullptr; jb.out[1] = V(2);
    jb.oldv[2] = nullptr; jb.out[2] = V(0);
    jb.oldv[3] = nullptr; jb.out[3] = V(1);
    stage2_kernel<<<s2g, 256>>>(jb, eps, 0, nn, nbands);

    // --- Sinkhorn iterations (ping-pong, blended epilogue) ---
    int cur = 0;
    for (int k = 0; k < L; k++) {
        int oth = cur ^ 4;
        sp.eps_idx = k;
        sp.potr[0] = V(cur + 3); sp.potc[0] = V(cur + 2);
        sp.potr[1] = V(cur + 0); sp.potc[1] = V(cur + 0);
        sp.potr[2] = V(cur + 1); sp.potc[2] = V(cur + 1);
        strip_kernel<<<totalBlocks, 256>>>(sp);
        jb.oldv[0] = V(cur + 3); jb.out[0] = V(oth + 3);
        jb.oldv[1] = V(cur + 2); jb.out[1] = V(oth + 2);
        jb.oldv[2] = V(cur + 0); jb.out[2] = V(oth + 0);
        jb.oldv[3] = V(cur + 1); jb.out[3] = V(oth + 1);
        stage2_kernel<<<s2g, 256>>>(jb, eps, k, nn, nbands);
        cur = oth;
    }

    // --- final extrapolation at eps_list[L-1] ---
    sp.eps_idx = L - 1;
    sp.potr[0] = V(cur + 3); sp.potc[0] = V(cur + 2);
    sp.potr[1] = V(cur + 0); sp.potc[1] = V(cur + 0);
    sp.potr[2] = V(cur + 1); sp.potc[2] = V(cur + 1);
    strip_kernel<<<totalBlocks, 256>>>(sp);
    jb.oldv[0] = nullptr; jb.out[0] = V(8);
    jb.oldv[1] = nullptr; jb.out[1] = V(9);
    jb.oldv[2] = nullptr; jb.out[2] = V(10);
    jb.oldv[3] = nullptr; jb.out[3] = V(11);
    stage2_kernel<<<s2g, 256>>>(jb, eps, L - 1, nn, nbands);

    final_reduce_kernel<<<1, 256>>>((float*)d_out, N);
#undef V
}

// round 14
// speedup vs baseline: 2.1723x; 1.0949x over previous
#include <cuda_runtime.h>
#include <math.h>
#include <stdint.h>

// ============================================================================
// Sinkhorn divergence, N=M=8192, D=64.
// Round 7: software-pipelined strip kernel.
//  - register double-buffer prefetch of next 128-col panel (hides DRAM latency)
//  - ONE __syncthreads per panel via parity-double-buffered smem merge
//  - EX2 via inline PTX, warp-uniform skip votes retained
// ============================================================================

#define NMAX  8192
#define DDIM  64
#define LOG2E 1.4426950408889634f
#define LN2   0.6931471805599453f
#define PW    136   // partial slots: 128 col-bands + 8 row-chunks

static __device__ float d_Cxy[(size_t)NMAX * NMAX];
static __device__ float d_Cxx[(size_t)NMAX * NMAX];   // upper tiles only
static __device__ float d_Cyy[(size_t)NMAX * NMAX];   // upper tiles only
static __device__ float d_sq[2][NMAX];
static __device__ float d_vec[12][NMAX];
static __device__ float2 d_P[3][(size_t)PW * NMAX];

__device__ __forceinline__ float ex2f(float x) {
    float y;
    asm("ex2.approx.ftz.f32 %0, %1;" : "=f"(y) : "f"(x));
    return y;
}
__device__ __forceinline__ float lg2f(float x) {
    float y;
    asm("lg2.approx.ftz.f32 %0, %1;" : "=f"(y) : "f"(x));
    return y;
}

// ---------------------------------------------------------------------------
__global__ void sqnorm_kernel(const float* __restrict__ X, float* __restrict__ out,
                              int n, int d) {
    int row = blockIdx.x * (blockDim.x >> 5) + (threadIdx.x >> 5);
    int lane = threadIdx.x & 31;
    if (row >= n) return;
    float s = 0.f;
    for (int c = lane; c < d; c += 32) {
        float v = X[(size_t)row * d + c];
        s += v * v;
    }
#pragma unroll
    for (int o = 16; o; o >>= 1) s += __shfl_xor_sync(0xFFFFFFFFu, s, o);
    if (lane == 0) out[row] = s;
}

// ---------------------------------------------------------------------------
#define BM 128
#define BKC 32

__global__ __launch_bounds__(256) void cost_gemm_kernel(
    const float* __restrict__ A, const float* __restrict__ B,
    const float* __restrict__ sqa, const float* __restrict__ sqb,
    float* __restrict__ C1, int nB, int d, int sym)
{
    int bj = blockIdx.x, bi = blockIdx.y;
    if (sym && bi > bj) return;

    __shared__ float As[BKC][BM + 4];
    __shared__ float Bs[BKC][BM + 4];

    int tid = threadIdx.x;
    int ti = tid & 15, tj = tid >> 4;
    int i0 = ti * 8, j0 = tj * 8;

    const float* Ab = A + (size_t)bi * BM * d;
    const float* Bb = B + (size_t)bj * BM * d;

    float acc[8][8];
#pragma unroll
    for (int a = 0; a < 8; a++)
#pragma unroll
        for (int b = 0; b < 8; b++) acc[a][b] = 0.f;

    for (int kk = 0; kk < d; kk += BKC) {
#pragma unroll
        for (int v = tid; v < 1024; v += 256) {
            int r = v >> 3, c4 = (v & 7) * 4;
            float4 a = *(const float4*)(Ab + (size_t)r * d + kk + c4);
            As[c4 + 0][r] = a.x; As[c4 + 1][r] = a.y;
            As[c4 + 2][r] = a.z; As[c4 + 3][r] = a.w;
            float4 b = *(const float4*)(Bb + (size_t)r * d + kk + c4);
            Bs[c4 + 0][r] = b.x; Bs[c4 + 1][r] = b.y;
            Bs[c4 + 2][r] = b.z; Bs[c4 + 3][r] = b.w;
        }
        __syncthreads();
#pragma unroll
        for (int k = 0; k < BKC; k++) {
            float4 a0 = *(const float4*)&As[k][i0];
            float4 a1 = *(const float4*)&As[k][i0 + 4];
            float4 b0 = *(const float4*)&Bs[k][j0];
            float4 b1 = *(const float4*)&Bs[k][j0 + 4];
            float av[8] = {a0.x, a0.y, a0.z, a0.w, a1.x, a1.y, a1.z, a1.w};
            float bv[8] = {b0.x, b0.y, b0.z, b0.w, b1.x, b1.y, b1.z, b1.w};
#pragma unroll
            for (int ii = 0; ii < 8; ii++)
#pragma unroll
                for (int jj = 0; jj < 8; jj++)
                    acc[ii][jj] += av[ii] * bv[jj];
        }
        __syncthreads();
    }

    float si[8], sj[8];
#pragma unroll
    for (int ii = 0; ii < 8; ii++) si[ii] = 0.5f * sqa[bi * BM + i0 + ii];
#pragma unroll
    for (int jj = 0; jj < 8; jj++) sj[jj] = 0.5f * sqb[bj * BM + j0 + jj];

#pragma unroll
    for (int ii = 0; ii < 8; ii++) {
        size_t off = (size_t)(bi * BM + i0 + ii) * nB + bj * BM + j0;
        float4 w0 = make_float4(
            fmaxf(si[ii] + sj[0] - acc[ii][0], 0.f),
            fmaxf(si[ii] + sj[1] - acc[ii][1], 0.f),
            fmaxf(si[ii] + sj[2] - acc[ii][2], 0.f),
            fmaxf(si[ii] + sj[3] - acc[ii][3], 0.f));
        float4 w1 = make_float4(
            fmaxf(si[ii] + sj[4] - acc[ii][4], 0.f),
            fmaxf(si[ii] + sj[5] - acc[ii][5], 0.f),
            fmaxf(si[ii] + sj[6] - acc[ii][6], 0.f),
            fmaxf(si[ii] + sj[7] - acc[ii][7], 0.f));
        *(float4*)(C1 + off) = w0;
        *(float4*)(C1 + off + 4) = w1;
    }
}

// ---------------------------------------------------------------------------
// strip kernel (software pipelined)
// ---------------------------------------------------------------------------
struct StripP {
    const float* C[3];
    float2*      P[3];
    const float* potr[3];
    const float* potc[3];
    float        lwr[3], lwc[3];
    const float* eps_list;
    int eps_idx;
    int nn, nbands, cpr, blocksXY, blocksSym;
};

__global__ __launch_bounds__(256, 2) void strip_kernel(StripP prm)
{
    int nn = prm.nn;
    int id = blockIdx.x;
    int mat, band, chunk;
    if (id < prm.blocksXY) {
        mat = 0;
        band = id / prm.cpr;
        chunk = id - band * prm.cpr;
    } else {
        id -= prm.blocksXY;
        mat = 1 + id / prm.blocksSym;
        int sid = id - (mat - 1) * prm.blocksSym;
        int b = 0;
        for (;;) {
            int nc = (prm.nbands - b + 15) >> 4;
            if (sid < nc) break;
            sid -= nc; b++;
        }
        band = b; chunk = sid;
    }
    int c0, c1;
    if (mat == 0) { c0 = chunk << 10; c1 = c0 + 1024; }
    else { c0 = (band << 6) + (chunk << 10); c1 = min(c0 + 1024, nn); }
    int row0 = band << 6;

    const float* __restrict__ C = prm.C[mat];
    float2* __restrict__ P = prm.P[mat];
    const float* potr = prm.potr[mat];
    const float* potc = prm.potc[mat];

    float eps = prm.eps_list[prm.eps_idx];
    float ie2 = LOG2E / eps;
    float lwr2 = prm.lwr[mat] * LOG2E;
    float lwc2 = prm.lwc[mat] * LOG2E;

    int w = threadIdx.x >> 5, l = threadIdx.x & 31;
    int rbase = row0 + w * 8;

    float har[8];
#pragma unroll
    for (int r = 0; r < 8; r++)
        har[r] = potr ? fmaf(potr[rbase + r], ie2, lwr2) : lwr2;

    float rmx[8], rs[8];
#pragma unroll
    for (int r = 0; r < 8; r++) { rmx[r] = -3.4e38f; rs[r] = 0.f; }

    __shared__ float2 smc[2][8][128];
    const float* Cb = C + (size_t)rbase * nn;

    // ---- macros for pipelined panel processing ----
#define LOADP(U, H, PP) do {                                                   \
        int _j = (PP) + l * 4;                                                 \
        _Pragma("unroll")                                                      \
        for (int _r = 0; _r < 8; _r++)                                         \
            U[_r] = *(const float4*)(Cb + (size_t)_r * nn + _j);               \
        if (potc) {                                                            \
            float4 _p = *(const float4*)(potc + _j);                           \
            H.x = fmaf(_p.x, ie2, lwc2); H.y = fmaf(_p.y, ie2, lwc2);          \
            H.z = fmaf(_p.z, ie2, lwc2); H.w = fmaf(_p.w, ie2, lwc2);          \
        } else H = make_float4(lwc2, lwc2, lwc2, lwc2);                        \
    } while (0)

#define PROCESS(U, H, PP, PAR) do {                                            \
        float cm0 = -3.4e38f, cm1 = -3.4e38f, cm2 = -3.4e38f, cm3 = -3.4e38f;  \
        _Pragma("unroll")                                                      \
        for (int r = 0; r < 8; r++) {                                          \
            U[r].x *= -ie2; U[r].y *= -ie2; U[r].z *= -ie2; U[r].w *= -ie2;    \
            float v0 = U[r].x + H.x, v1 = U[r].y + H.y;                        \
            float v2 = U[r].z + H.z, v3 = U[r].w + H.w;                        \
            float m4 = fmaxf(fmaxf(v0, v1), fmaxf(v2, v3));                    \
            if (__any_sync(0xFFFFFFFFu, m4 > rmx[r] - 24.f)) {                 \
                float mn = fmaxf(rmx[r], m4);                                  \
                float e = ex2f(v0 - mn) + ex2f(v1 - mn)                        \
                        + ex2f(v2 - mn) + ex2f(v3 - mn);                       \
                rs[r] = fmaf(rs[r], ex2f(rmx[r] - mn), e);                     \
                rmx[r] = mn;                                                   \
            }                                                                  \
            float a = har[r];                                                  \
            cm0 = fmaxf(cm0, U[r].x + a); cm1 = fmaxf(cm1, U[r].y + a);        \
            cm2 = fmaxf(cm2, U[r].z + a); cm3 = fmaxf(cm3, U[r].w + a);        \
        }                                                                      \
        float cs0 = 0.f, cs1 = 0.f, cs2 = 0.f, cs3 = 0.f;                      \
        _Pragma("unroll")                                                      \
        for (int r = 0; r < 8; r++) {                                          \
            float t0 = har[r] - cm0, t1 = har[r] - cm1;                        \
            float t2 = har[r] - cm2, t3 = har[r] - cm3;                        \
            float w0 = U[r].x + t0, w1 = U[r].y + t1;                          \
            float w2 = U[r].z + t2, w3 = U[r].w + t3;                          \
            float m4c = fmaxf(fmaxf(w0, w1), fmaxf(w2, w3));                   \
            if (__any_sync(0xFFFFFFFFu, m4c > -24.f)) {                        \
                cs0 += ex2f(w0); cs1 += ex2f(w1);                              \
                cs2 += ex2f(w2); cs3 += ex2f(w3);                              \
            }                                                                  \
        }                                                                      \
        smc[PAR][w][l * 4 + 0] = make_float2(cm0, cs0);                       \
        smc[PAR][w][l * 4 + 1] = make_float2(cm1, cs1);                       \
        smc[PAR][w][l * 4 + 2] = make_float2(cm2, cs2);                       \
        smc[PAR][w][l * 4 + 3] = make_float2(cm3, cs3);                       \
        __syncthreads();                                                       \
        if (threadIdx.x < 128) {                                               \
            int cc = threadIdx.x;                                              \
            float2 a = smc[PAR][0][cc];                                        \
            float m = a.x, s = a.y;                                            \
            _Pragma("unroll")                                                  \
            for (int ww = 1; ww < 8; ww++) {                                   \
                float2 b = smc[PAR][ww][cc];                                   \
                float mn = fmaxf(m, b.x);                                      \
                s = fmaf(s, ex2f(m - mn), b.y * ex2f(b.x - mn));               \
                m = mn;                                                        \
            }                                                                  \
            int jj = (PP) + cc;                                                \
            if (!(mat && ((jj >> 6) == band)))                                 \
                P[(size_t)band * nn + jj] = make_float2(m, s);                 \
        }                                                                      \
    } while (0)

    // ---- pipelined loop over full 128-col panels ----
    float4 u[8], un[8], hcur, hn;
    int p = c0, par = 0;
    if (p + 128 <= c1) LOADP(u, hcur, p);
    while (p + 128 <= c1) {
        int pn = p + 128;
        if (pn + 128 <= c1) LOADP(un, hn, pn);   // prefetch next panel
        PROCESS(u, hcur, p, par);
#pragma unroll
        for (int r = 0; r < 8; r++) u[r] = un[r];
        hcur = hn;
        par ^= 1;
        p = pn;
    }

    // ---- 64-col tail panel ----
    if (p < c1) {
        int j = p + l * 2;
        float2 u2[8];
#pragma unroll
        for (int r = 0; r < 8; r++)
            u2[r] = *(const float2*)(Cb + (size_t)r * nn + j);
        float h0 = lwc2, h1 = lwc2;
        if (potc) {
            h0 = fmaf(potc[j], ie2, lwc2);
            h1 = fmaf(potc[j + 1], ie2, lwc2);
        }
        float cm0 = -3.4e38f, cm1 = -3.4e38f;
#pragma unroll
        for (int r = 0; r < 8; r++) {
            u2[r].x *= -ie2; u2[r].y *= -ie2;
            float v0 = u2[r].x + h0, v1 = u2[r].y + h1;
            float m2v = fmaxf(v0, v1);
            if (__any_sync(0xFFFFFFFFu, m2v > rmx[r] - 24.f)) {
                float mn = fmaxf(rmx[r], m2v);
                float e = ex2f(v0 - mn) + ex2f(v1 - mn);
                rs[r] = fmaf(rs[r], ex2f(rmx[r] - mn), e);
                rmx[r] = mn;
            }
            float a = har[r];
            cm0 = fmaxf(cm0, u2[r].x + a);
            cm1 = fmaxf(cm1, u2[r].y + a);
        }
        float cs0 = 0.f, cs1 = 0.f;
#pragma unroll
        for (int r = 0; r < 8; r++) {
            float a = har[r];
            float w0 = u2[r].x + a - cm0, w1 = u2[r].y + a - cm1;
            float m2c = fmaxf(w0, w1);
            if (__any_sync(0xFFFFFFFFu, m2c > -24.f)) {
                cs0 += ex2f(w0); cs1 += ex2f(w1);
            }
        }
        smc[par][w][l * 2 + 0] = make_float2(cm0, cs0);
        smc[par][w][l * 2 + 1] = make_float2(cm1, cs1);
        __syncthreads();
        if (threadIdx.x < 64) {
            int cc = threadIdx.x;
            float2 a = smc[par][0][cc];
            float m = a.x, s = a.y;
#pragma unroll
            for (int ww = 1; ww < 8; ww++) {
                float2 b = smc[par][ww][cc];
                float mn = fmaxf(m, b.x);
                s = fmaf(s, ex2f(m - mn), b.y * ex2f(b.x - mn));
                m = mn;
            }
            int jj = p + cc;
            if (!(mat && ((jj >> 6) == band)))
                P[(size_t)band * nn + jj] = make_float2(m, s);
        }
        __syncthreads();
    }

    // ---- row partial output (once per chunk) ----
#pragma unroll
    for (int r = 0; r < 8; r++) {
        float m = rmx[r], s = rs[r];
#pragma unroll
        for (int o = 16; o; o >>= 1) {
            float m2 = __shfl_xor_sync(0xFFFFFFFFu, m, o);
            float s2 = __shfl_xor_sync(0xFFFFFFFFu, s, o);
            float mn = fmaxf(m, m2);
            s = fmaf(s, ex2f(m - mn), s2 * ex2f(m2 - mn));
            m = mn;
        }
        if (l == 0)
            P[(size_t)(prm.nbands + chunk) * nn + rbase + r] = make_float2(m, s);
    }
#undef LOADP
#undef PROCESS
}

// ---------------------------------------------------------------------------
struct S2J {
    const float2* P[4];
    const float*  oldv[4];
    float*        out[4];
    int colLim[4];
    int chLim[4];
};

__global__ __launch_bounds__(256) void stage2_kernel(
    S2J jb, const float* __restrict__ eps_list, int eps_idx, int nn, int nbands)
{
    int job = blockIdx.y;
    int row = blockIdx.x * 256 + threadIdx.x;
    float eps = eps_list[eps_idx];
    const float2* __restrict__ P = jb.P[job];
    int band = row >> 6;
    int cl = jb.colLim[job]; if (cl < 0) cl = band;
    int ch = jb.chLim[job];  if (ch < 0) ch = (nbands - band + 15) >> 4;

    float mx = -3.4e38f, s = 0.f;
    for (int t = 0; t < cl; t++) {
        float2 p = P[(size_t)t * nn + row];
        float mn = fmaxf(mx, p.x);
        s = fmaf(s, ex2f(mx - mn), p.y * ex2f(p.x - mn));
        mx = mn;
    }
    for (int t = 0; t < ch; t++) {
        float2 p = P[(size_t)(nbands + t) * nn + row];
        float mn = fmaxf(mx, p.x);
        s = fmaf(s, ex2f(mx - mn), p.y * ex2f(p.x - mn));
        mx = mn;
    }
    float res = -eps * LN2 * (mx + lg2f(s));
    const float* ov = jb.oldv[job];
    jb.out[job][row] = ov ? 0.5f * (ov[row] + res) : res;
}

// ---------------------------------------------------------------------------
__global__ void final_reduce_kernel(float* __restrict__ out, int n) {
    __shared__ float red[256];
    float s = 0.f;
    for (int i = threadIdx.x; i < n; i += 256)
        s += (d_vec[8][i] - d_vec[10][i]) + (d_vec[9][i] - d_vec[11][i]);
    red[threadIdx.x] = s;
    __syncthreads();
    for (int o = 128; o; o >>= 1) {
        if (threadIdx.x < o) red[threadIdx.x] += red[threadIdx.x + o];
        __syncthreads();
    }
    if (threadIdx.x == 0) out[0] = red[0] / (float)n;
}

// ---------------------------------------------------------------------------
extern "C" void kernel_launch(void* const* d_in, const int* in_sizes, int n_in,
                              void* d_out, int out_size) {
    const float* gx = (const float*)d_in[0];
    const float* gy = (const float*)d_in[1];
    const float* eps = (const float*)d_in[2];
    int N = in_sizes[0] / DDIM;
    int M = in_sizes[1] / DDIM;
    int L = in_sizes[2];
    if (N > NMAX || M > NMAX || N != M) return;
    int nn = N;

    float *Cxy, *Cxx, *Cyy, *sq, *vec;
    float2* Pbase;
    cudaGetSymbolAddress((void**)&Cxy, d_Cxy);
    cudaGetSymbolAddress((void**)&Cxx, d_Cxx);
    cudaGetSymbolAddress((void**)&Cyy, d_Cyy);
    cudaGetSymbolAddress((void**)&sq, d_sq);
    cudaGetSymbolAddress((void**)&vec, d_vec);
    cudaGetSymbolAddress((void**)&Pbase, d_P);
    float* sqx = sq;
    float* sqy = sq + NMAX;
    float2* P0 = Pbase;
    float2* P1 = Pbase + (size_t)PW * NMAX;
    float2* P2 = Pbase + 2 * (size_t)PW * NMAX;
#define V(i) (vec + (size_t)(i) * NMAX)

    float alog = -logf((float)N);
    float blog = -logf((float)M);

    sqnorm_kernel<<<(N + 7) / 8, 256>>>(gx, sqx, N, DDIM);
    sqnorm_kernel<<<(M + 7) / 8, 256>>>(gy, sqy, M, DDIM);
    cost_gemm_kernel<<<dim3(M / BM, N / BM), 256>>>(gx, gy, sqx, sqy, Cxy, M, DDIM, 0);
    cost_gemm_kernel<<<dim3(N / BM, N / BM), 256>>>(gx, gx, sqx, sqx, Cxx, N, DDIM, 1);
    cost_gemm_kernel<<<dim3(M / BM, M / BM), 256>>>(gy, gy, sqy, sqy, Cyy, M, DDIM, 1);

    int nbands = nn / 64;
    int cpr = nn / 1024;
    int blocksXY = nbands * cpr;
    int S = 0;
    for (int b = 0; b < nbands; b++) S += (nbands - b + 15) >> 4;
    int totalBlocks = blocksXY + 2 * S;

    StripP sp;
    sp.C[0] = Cxy; sp.C[1] = Cxx; sp.C[2] = Cyy;
    sp.P[0] = P0;  sp.P[1] = P1;  sp.P[2] = P2;
    sp.lwr[0] = alog; sp.lwc[0] = blog;
    sp.lwr[1] = alog; sp.lwc[1] = alog;
    sp.lwr[2] = blog; sp.lwc[2] = blog;
    sp.eps_list = eps;
    sp.nn = nn; sp.nbands = nbands; sp.cpr = cpr;
    sp.blocksXY = blocksXY; sp.blocksSym = S;

    S2J jb;
    jb.P[0] = P0; jb.colLim[0] = 0;      jb.chLim[0] = cpr;
    jb.P[1] = P0; jb.colLim[1] = nbands; jb.chLim[1] = 0;
    jb.P[2] = P1; jb.colLim[2] = -1;     jb.chLim[2] = -1;
    jb.P[3] = P2; jb.colLim[3] = -1;     jb.chLim[3] = -1;

    dim3 s2g(nn / 256, 4);

    // init
    sp.eps_idx = 0;
    sp.potr[0] = nullptr; sp.potc[0] = nullptr;
    sp.potr[1] = nullptr; sp.potc[1] = nullptr;
    sp.potr[2] = nullptr; sp.potc[2] = nullptr;
    strip_kernel<<<totalBlocks, 256>>>(sp);
    jb.oldv[0] = nullptr; jb.out[0] = V(3);
    jb.oldv[1] = nullptr; jb.out[1] = V(2);
    jb.oldv[2] = nullptr; jb.out[2] = V(0);
    jb.oldv[3] = nullptr; jb.out[3] = V(1);
    stage2_kernel<<<s2g, 256>>>(jb, eps, 0, nn, nbands);

    // iterations
    int cur = 0;
    for (int k = 0; k < L; k++) {
        int oth = cur ^ 4;
        sp.eps_idx = k;
        sp.potr[0] = V(cur + 3); sp.potc[0] = V(cur + 2);
        sp.potr[1] = V(cur + 0); sp.potc[1] = V(cur + 0);
        sp.potr[2] = V(cur + 1); sp.potc[2] = V(cur + 1);
        strip_kernel<<<totalBlocks, 256>>>(sp);
        jb.oldv[0] = V(cur + 3); jb.out[0] = V(oth + 3);
        jb.oldv[1] = V(cur + 2); jb.out[1] = V(oth + 2);
        jb.oldv[2] = V(cur + 0); jb.out[2] = V(oth + 0);
        jb.oldv[3] = V(cur + 1); jb.out[3] = V(oth + 1);
        stage2_kernel<<<s2g, 256>>>(jb, eps, k, nn, nbands);
        cur = oth;
    }

    // final extrapolation
    sp.eps_idx = L - 1;
    sp.potr[0] = V(cur + 3); sp.potc[0] = V(cur + 2);
    sp.potr[1] = V(cur + 0); sp.potc[1] = V(cur + 0);
    sp.potr[2] = V(cur + 1); sp.potc[2] = V(cur + 1);
    strip_kernel<<<totalBlocks, 256>>>(sp);
    jb.oldv[0] = nullptr; jb.out[0] = V(8);
    jb.oldv[1] = nullptr; jb.out[1] = V(9);
    jb.oldv[2] = nullptr; jb.out[2] = V(10);
    jb.oldv[3] = nullptr; jb.out[3] = V(11);
    stage2_kernel<<<s2g, 256>>>(jb, eps, L - 1, nn, nbands);

    final_reduce_kernel<<<1, 256>>>((float*)d_out, N);
#undef V
}